// round 3
// baseline (speedup 1.0000x reference)
#include <cuda_runtime.h>
#include <math.h>

#define BATCH 2
#define SEQ   2048
#define NH    16
#define HD    64
#define DM    1024
#define MROWS (BATCH*SEQ)   /* 4096 */

/* ------------------------------------------------------------------ */
/* scratch (static device globals: allowed; no runtime allocation)     */
/* ------------------------------------------------------------------ */
__device__ float g_q[(size_t)BATCH * NH * SEQ * HD];   /* [b,h,s,d] */
__device__ float g_k[(size_t)BATCH * NH * SEQ * HD];
__device__ float g_v[(size_t)BATCH * NH * SEQ * HD];
__device__ float g_att[(size_t)MROWS * DM];            /* [b,s,h*d] */
__device__ float g_rope[SEQ * 32 * 2];                 /* [s][pair][cos,sin] */

/* ------------------------------------------------------------------ */
/* RoPE table: accurate double-precision range reduction               */
/* ------------------------------------------------------------------ */
__global__ void rope_fill(const int* __restrict__ pos)
{
    int idx = blockIdx.x * blockDim.x + threadIdx.x;
    if (idx >= SEQ * 32) return;
    int s = idx >> 5, p = idx & 31;
    float ff  = (float)(1.0 / pow(10000.0, (double)(2 * p) / 64.0));
    float ang = (float)pos[s] * ff;           /* fp32 product, like the reference */
    double a  = (double)ang;
    g_rope[idx * 2 + 0] = (float)cos(a);
    g_rope[idx * 2 + 1] = (float)sin(a);
}

/* ------------------------------------------------------------------ */
/* SGEMM: C = A[4096,1024] @ Bw[1024,1024]^T                           */
/* mode 0: plain row-major C[m,n]                                      */
/* mode 1: write [b,h,s,d] with RoPE (Q,K)                             */
/* mode 2: write [b,h,s,d] without RoPE (V)                            */
/* ------------------------------------------------------------------ */
__global__ __launch_bounds__(256) void sgemm_k(const float* __restrict__ A,
                                               const float* __restrict__ Bw,
                                               float* __restrict__ C, int mode)
{
    const int K = DM, N = DM;
    __shared__ float As[8][128];
    __shared__ float Bs[8][128];

    int t  = threadIdx.x;
    int m0 = blockIdx.y * 128, n0 = blockIdx.x * 128;
    int tr = t >> 4, tc = t & 15;
    int lr = t >> 1;
    int lc = (t & 1) * 4;

    const float* Ap = A  + (size_t)(m0 + lr) * K + lc;
    const float* Bp = Bw + (size_t)(n0 + lr) * K + lc;

    float acc[8][8];
#pragma unroll
    for (int i = 0; i < 8; i++)
#pragma unroll
        for (int j = 0; j < 8; j++) acc[i][j] = 0.0f;

    for (int k0 = 0; k0 < K; k0 += 8) {
        float4 av = *(const float4*)(Ap + k0);
        float4 bv = *(const float4*)(Bp + k0);
        As[lc + 0][lr] = av.x; As[lc + 1][lr] = av.y;
        As[lc + 2][lr] = av.z; As[lc + 3][lr] = av.w;
        Bs[lc + 0][lr] = bv.x; Bs[lc + 1][lr] = bv.y;
        Bs[lc + 2][lr] = bv.z; Bs[lc + 3][lr] = bv.w;
        __syncthreads();
#pragma unroll
        for (int kk = 0; kk < 8; kk++) {
            float4 a0 = *(const float4*)&As[kk][tr * 4];
            float4 a1 = *(const float4*)&As[kk][64 + tr * 4];
            float4 b0 = *(const float4*)&Bs[kk][tc * 4];
            float4 b1 = *(const float4*)&Bs[kk][64 + tc * 4];
            float ar[8] = {a0.x, a0.y, a0.z, a0.w, a1.x, a1.y, a1.z, a1.w};
            float br[8] = {b0.x, b0.y, b0.z, b0.w, b1.x, b1.y, b1.z, b1.w};
#pragma unroll
            for (int i = 0; i < 8; i++)
#pragma unroll
                for (int j = 0; j < 8; j++)
                    acc[i][j] = fmaf(ar[i], br[j], acc[i][j]);
        }
        __syncthreads();
    }

#pragma unroll
    for (int i = 0; i < 8; i++) {
        int gm = m0 + ((i < 4) ? (tr * 4 + i) : (64 + tr * 4 + (i - 4)));
#pragma unroll
        for (int jh = 0; jh < 2; jh++) {
            int gn = n0 + ((jh == 0) ? (tc * 4) : (64 + tc * 4));
            float v0 = acc[i][jh * 4 + 0], v1 = acc[i][jh * 4 + 1];
            float v2 = acc[i][jh * 4 + 2], v3 = acc[i][jh * 4 + 3];
            if (mode == 0) {
                *(float4*)(C + (size_t)gm * N + gn) = make_float4(v0, v1, v2, v3);
            } else {
                int b = gm >> 11, s = gm & (SEQ - 1);
                int h = gn >> 6,  d = gn & 63;
                if (mode == 1) {
                    int p0 = d >> 1;                    /* 4 cols => pairs p0, p0+1 */
                    float c0 = g_rope[(s * 32 + p0) * 2 + 0];
                    float s0 = g_rope[(s * 32 + p0) * 2 + 1];
                    float c1 = g_rope[(s * 32 + p0 + 1) * 2 + 0];
                    float s1 = g_rope[(s * 32 + p0 + 1) * 2 + 1];
                    float e0 = v0 * c0 - v1 * s0, o0 = v0 * s0 + v1 * c0;
                    float e1 = v2 * c1 - v3 * s1, o1 = v2 * s1 + v3 * c1;
                    v0 = e0; v1 = o0; v2 = e1; v3 = o1;
                }
                size_t dst = (((size_t)(b * NH + h) * SEQ) + s) * HD + d;
                *(float4*)(C + dst) = make_float4(v0, v1, v2, v3);
            }
        }
    }
}

/* ------------------------------------------------------------------ */
/* Flash attention, fp32. 64 queries x 64 keys per inner tile.         */
/* Q,K stored d-major (transposed) in smem with XOR swizzle so both    */
/* GEMMs are outer-products from LDS.128.                              */
/* ------------------------------------------------------------------ */
#define FSTR 68
#define SW(kk, r) ((r) ^ (((((kk) >> 2)) & 7) << 2))
#define FLASH_SMEM (4 * 64 * FSTR * (int)sizeof(float))

__global__ __launch_bounds__(256) void flash_k(const float* __restrict__ gq,
                                               const float* __restrict__ gk,
                                               const float* __restrict__ gv,
                                               float* __restrict__ gout)
{
    extern __shared__ float sm[];
    float* Qst = sm;                 /* [d=64][FSTR] swizzled */
    float* Kst = sm + 64 * FSTR;     /* [d=64][FSTR] swizzled */
    float* Vs  = sm + 2 * 64 * FSTR; /* [c=64][FSTR] natural  */
    float* Ps  = sm + 3 * 64 * FSTR; /* [r=64][FSTR] natural  */

    int t  = threadIdx.x;
    int qt = blockIdx.x;             /* 0..31 query tile      */
    int bh = blockIdx.y;             /* 0..31 (b*NH + h)      */

    const float* Qg = gq + ((size_t)bh * SEQ + qt * 64) * HD;

    /* load Q tile transposed (coalesced GMEM, ~2-way STS conflict) */
    for (int idx = t; idx < 64 * 16; idx += 256) {
        int r = idx >> 4, c4 = (idx & 15) * 4;
        float4 v = *(const float4*)(Qg + r * HD + c4);
        Qst[(c4 + 0) * FSTR + SW(c4 + 0, r)] = v.x;
        Qst[(c4 + 1) * FSTR + SW(c4 + 1, r)] = v.y;
        Qst[(c4 + 2) * FSTR + SW(c4 + 2, r)] = v.z;
        Qst[(c4 + 3) * FSTR + SW(c4 + 3, r)] = v.w;
    }

    int ty = t >> 4, tx = t & 15;
    int r0 = ty * 4, c0 = tx * 4;

    float m_i[4], l_i[4], O[4][4];
#pragma unroll
    for (int i = 0; i < 4; i++) {
        m_i[i] = -1e30f; l_i[i] = 0.0f;
#pragma unroll
        for (int j = 0; j < 4; j++) O[i][j] = 0.0f;
    }
    const unsigned FULL = 0xffffffffu;
    const float scale = 0.125f;      /* 1/sqrt(64) */

    for (int kt = 0; kt <= qt; kt++) {
        __syncthreads();             /* protect smem from previous iter + Q load */
        const float* Kg = gk + ((size_t)bh * SEQ + kt * 64) * HD;
        const float* Vg = gv + ((size_t)bh * SEQ + kt * 64) * HD;
        for (int idx = t; idx < 64 * 16; idx += 256) {
            int r = idx >> 4, c4 = (idx & 15) * 4;
            float4 kv = *(const float4*)(Kg + r * HD + c4);
            Kst[(c4 + 0) * FSTR + SW(c4 + 0, r)] = kv.x;
            Kst[(c4 + 1) * FSTR + SW(c4 + 1, r)] = kv.y;
            Kst[(c4 + 2) * FSTR + SW(c4 + 2, r)] = kv.z;
            Kst[(c4 + 3) * FSTR + SW(c4 + 3, r)] = kv.w;
            float4 vv = *(const float4*)(Vg + r * HD + c4);
            *(float4*)(Vs + r * FSTR + c4) = vv;
        }
        __syncthreads();

        /* S = Q K^T, outer product over d */
        float sacc[4][4];
#pragma unroll
        for (int i = 0; i < 4; i++)
#pragma unroll
            for (int j = 0; j < 4; j++) sacc[i][j] = 0.0f;
#pragma unroll 16
        for (int kk = 0; kk < 64; kk++) {
            float4 qf = *(const float4*)(Qst + kk * FSTR + SW(kk, r0));
            float4 kf = *(const float4*)(Kst + kk * FSTR + SW(kk, c0));
            float qa[4] = {qf.x, qf.y, qf.z, qf.w};
            float ka[4] = {kf.x, kf.y, kf.z, kf.w};
#pragma unroll
            for (int i = 0; i < 4; i++)
#pragma unroll
                for (int j = 0; j < 4; j++)
                    sacc[i][j] = fmaf(qa[i], ka[j], sacc[i][j]);
        }

        /* scale + causal mask */
        int gi0 = qt * 64 + r0, gj0 = kt * 64 + c0;
#pragma unroll
        for (int i = 0; i < 4; i++)
#pragma unroll
            for (int j = 0; j < 4; j++) {
                float s = sacc[i][j] * scale;
                sacc[i][j] = (gj0 + j > gi0 + i) ? -1e30f : s;
            }

        /* online softmax, rows reduced across the 16 column-threads */
#pragma unroll
        for (int i = 0; i < 4; i++) {
            float mt = fmaxf(fmaxf(sacc[i][0], sacc[i][1]),
                             fmaxf(sacc[i][2], sacc[i][3]));
#pragma unroll
            for (int off = 8; off > 0; off >>= 1)
                mt = fmaxf(mt, __shfl_xor_sync(FULL, mt, off));
            float mnew = fmaxf(m_i[i], mt);
            float al = __expf(m_i[i] - mnew);
            float ps = 0.0f;
#pragma unroll
            for (int j = 0; j < 4; j++) {
                float p = __expf(sacc[i][j] - mnew);
                sacc[i][j] = p; ps += p;
            }
#pragma unroll
            for (int off = 8; off > 0; off >>= 1)
                ps += __shfl_xor_sync(FULL, ps, off);
            l_i[i] = l_i[i] * al + ps;
            m_i[i] = mnew;
#pragma unroll
            for (int j = 0; j < 4; j++) O[i][j] *= al;
        }

        /* write P (conflict-free float4) */
#pragma unroll
        for (int i = 0; i < 4; i++)
            *(float4*)(Ps + (r0 + i) * FSTR + c0) =
                make_float4(sacc[i][0], sacc[i][1], sacc[i][2], sacc[i][3]);
        __syncthreads();

        /* O += P V, vectorized over 4 keys at a time */
#pragma unroll 4
        for (int c = 0; c < 64; c += 4) {
            float4 pv[4], vf[4];
#pragma unroll
            for (int i = 0; i < 4; i++)
                pv[i] = *(const float4*)(Ps + (r0 + i) * FSTR + c);
#pragma unroll
            for (int jj = 0; jj < 4; jj++)
                vf[jj] = *(const float4*)(Vs + (c + jj) * FSTR + c0);
#pragma unroll
            for (int i = 0; i < 4; i++) {
                O[i][0] += pv[i].x * vf[0].x + pv[i].y * vf[1].x
                         + pv[i].z * vf[2].x + pv[i].w * vf[3].x;
                O[i][1] += pv[i].x * vf[0].y + pv[i].y * vf[1].y
                         + pv[i].z * vf[2].y + pv[i].w * vf[3].y;
                O[i][2] += pv[i].x * vf[0].z + pv[i].y * vf[1].z
                         + pv[i].z * vf[2].z + pv[i].w * vf[3].z;
                O[i][3] += pv[i].x * vf[0].w + pv[i].y * vf[1].w
                         + pv[i].z * vf[2].w + pv[i].w * vf[3].w;
            }
        }
    }

    /* normalize + write in [b, s, h*64+d] layout for the output GEMM */
    int b = bh >> 4, h = bh & 15;
#pragma unroll
    for (int i = 0; i < 4; i++) {
        int s = qt * 64 + r0 + i;
        float inv = 1.0f / l_i[i];
        size_t dst = ((size_t)b * SEQ + s) * DM + h * HD + c0;
        *(float4*)(gout + dst) = make_float4(O[i][0] * inv, O[i][1] * inv,
                                             O[i][2] * inv, O[i][3] * inv);
    }
}

/* ------------------------------------------------------------------ */
extern "C" void kernel_launch(void* const* d_in, const int* in_sizes, int n_in,
                              void* d_out, int out_size)
{
    const float* x  = (const float*)d_in[0];
    const float* Wq = (const float*)d_in[1];
    const float* Wk = (const float*)d_in[2];
    const float* Wv = (const float*)d_in[3];
    const float* Wo = (const float*)d_in[4];
    /* d_in[5] = causal mask (tril by construction; handled analytically) */
    const int*   pos = (const int*)d_in[6];
    float* out = (float*)d_out;

    float *q, *k, *v, *att;
    cudaGetSymbolAddress((void**)&q,   g_q);
    cudaGetSymbolAddress((void**)&k,   g_k);
    cudaGetSymbolAddress((void**)&v,   g_v);
    cudaGetSymbolAddress((void**)&att, g_att);

    cudaFuncSetAttribute(flash_k, cudaFuncAttributeMaxDynamicSharedMemorySize,
                         FLASH_SMEM);

    rope_fill<<<256, 256>>>(pos);

    dim3 gg(DM / 128, MROWS / 128);  /* (8, 32) */
    sgemm_k<<<gg, 256>>>(x, Wq, q, 1);
    sgemm_k<<<gg, 256>>>(x, Wk, k, 1);
    sgemm_k<<<gg, 256>>>(x, Wv, v, 2);

    flash_k<<<dim3(SEQ / 64, BATCH * NH), 256, FLASH_SMEM>>>(q, k, v, att);

    sgemm_k<<<gg, 256>>>(att, Wo, out, 0);
}

// round 5
// speedup vs baseline: 2.8919x; 2.8919x over previous
#include <cuda_runtime.h>
#include <math.h>

#define BATCH 2
#define SEQ   2048
#define NH    16
#define HD    64
#define DM    1024
#define MROWS (BATCH*SEQ)   /* 4096 */

/* ------------------------------------------------------------------ */
/* scratch                                                             */
/* ------------------------------------------------------------------ */
__device__ float g_q[(size_t)BATCH * NH * SEQ * HD];   /* [b,h,s,d] */
__device__ float g_k[(size_t)BATCH * NH * SEQ * HD];
__device__ float g_v[(size_t)BATCH * NH * SEQ * HD];
__device__ float g_att[(size_t)MROWS * DM];            /* [b,s,h*d] */
__device__ float g_rope[SEQ * 32 * 2];                 /* [s][pair][cos,sin] */

/* ------------------------------------------------------------------ */
__device__ __forceinline__ unsigned f2tf(float x)
{
    unsigned u;
    asm("cvt.rna.tf32.f32 %0, %1;" : "=r"(u) : "f"(x));
    return u;
}

__device__ __forceinline__ void mma8(float* c,
                                     unsigned a0, unsigned a1, unsigned a2, unsigned a3,
                                     unsigned b0, unsigned b1)
{
    asm("mma.sync.aligned.m16n8k8.row.col.f32.tf32.tf32.f32 "
        "{%0,%1,%2,%3},{%4,%5,%6,%7},{%8,%9},{%0,%1,%2,%3};"
        : "+f"(c[0]), "+f"(c[1]), "+f"(c[2]), "+f"(c[3])
        : "r"(a0), "r"(a1), "r"(a2), "r"(a3), "r"(b0), "r"(b1));
}

/* ------------------------------------------------------------------ */
/* RoPE table                                                          */
/* ------------------------------------------------------------------ */
__global__ void rope_fill(const int* __restrict__ pos)
{
    int idx = blockIdx.x * blockDim.x + threadIdx.x;
    if (idx >= SEQ * 32) return;
    int s = idx >> 5, p = idx & 31;
    float ff  = (float)(1.0 / pow(10000.0, (double)(2 * p) / 64.0));
    float ang = (float)pos[s] * ff;
    double a  = (double)ang;
    g_rope[idx * 2 + 0] = (float)cos(a);
    g_rope[idx * 2 + 1] = (float)sin(a);
}

/* ------------------------------------------------------------------ */
/* TF32 tensor-core GEMM: C = A[4096,1024] @ Bw[1024,1024]^T           */
/* mode 0: row-major C; mode 1: [b,h,s,d]+RoPE; mode 2: [b,h,s,d]      */
/* ------------------------------------------------------------------ */
#define BK 16
#define KS (BK + 4)   /* smem k-stride: 20 words, 20%32 -> conflict-free frags */

__global__ __launch_bounds__(256) void gemm_tc(const float* __restrict__ A,
                                               const float* __restrict__ Bw,
                                               float* __restrict__ C, int mode)
{
    __shared__ unsigned As[2][128][KS];
    __shared__ unsigned Bs[2][128][KS];

    int t = threadIdx.x, lane = t & 31, wid = t >> 5;
    int g = lane >> 2, tq = lane & 3;
    int wm = (wid & 1) * 64, wn = (wid >> 1) * 32;
    int m0 = blockIdx.y * 128, n0 = blockIdx.x * 128;

    int lr = t >> 2;          /* 0..63 */
    int lk = (t & 3) * 4;
    const float* Ap = A  + (size_t)(m0 + lr) * DM + lk;
    const float* Bp = Bw + (size_t)(n0 + lr) * DM + lk;

    float acc[4][4][4];
#pragma unroll
    for (int mf = 0; mf < 4; mf++)
#pragma unroll
        for (int nf = 0; nf < 4; nf++)
#pragma unroll
            for (int i = 0; i < 4; i++) acc[mf][nf][i] = 0.0f;

    float4 a0v, a1v, b0v, b1v;
    a0v = *(const float4*)(Ap);
    a1v = *(const float4*)(Ap + 64 * DM);
    b0v = *(const float4*)(Bp);
    b1v = *(const float4*)(Bp + 64 * DM);
    *(uint4*)&As[0][lr][lk]      = make_uint4(f2tf(a0v.x), f2tf(a0v.y), f2tf(a0v.z), f2tf(a0v.w));
    *(uint4*)&As[0][lr + 64][lk] = make_uint4(f2tf(a1v.x), f2tf(a1v.y), f2tf(a1v.z), f2tf(a1v.w));
    *(uint4*)&Bs[0][lr][lk]      = make_uint4(f2tf(b0v.x), f2tf(b0v.y), f2tf(b0v.z), f2tf(b0v.w));
    *(uint4*)&Bs[0][lr + 64][lk] = make_uint4(f2tf(b1v.x), f2tf(b1v.y), f2tf(b1v.z), f2tf(b1v.w));
    __syncthreads();

#pragma unroll 1
    for (int c = 0; c < DM / BK; c++) {
        int buf = c & 1;
        if (c + 1 < DM / BK) {
            int off = (c + 1) * BK;
            a0v = *(const float4*)(Ap + off);
            a1v = *(const float4*)(Ap + 64 * DM + off);
            b0v = *(const float4*)(Bp + off);
            b1v = *(const float4*)(Bp + 64 * DM + off);
        }
#pragma unroll
        for (int ks = 0; ks < 2; ks++) {
            int k = ks * 8 + tq;
            unsigned af[4][4], bf[4][2];
#pragma unroll
            for (int mf = 0; mf < 4; mf++) {
                int r = wm + mf * 16 + g;
                af[mf][0] = As[buf][r][k];
                af[mf][1] = As[buf][r + 8][k];
                af[mf][2] = As[buf][r][k + 4];
                af[mf][3] = As[buf][r + 8][k + 4];
            }
#pragma unroll
            for (int nf = 0; nf < 4; nf++) {
                int n = wn + nf * 8 + g;
                bf[nf][0] = Bs[buf][n][k];
                bf[nf][1] = Bs[buf][n][k + 4];
            }
#pragma unroll
            for (int mf = 0; mf < 4; mf++)
#pragma unroll
                for (int nf = 0; nf < 4; nf++)
                    mma8(acc[mf][nf], af[mf][0], af[mf][1], af[mf][2], af[mf][3],
                         bf[nf][0], bf[nf][1]);
        }
        if (c + 1 < DM / BK) {
            int nb = buf ^ 1;
            *(uint4*)&As[nb][lr][lk]      = make_uint4(f2tf(a0v.x), f2tf(a0v.y), f2tf(a0v.z), f2tf(a0v.w));
            *(uint4*)&As[nb][lr + 64][lk] = make_uint4(f2tf(a1v.x), f2tf(a1v.y), f2tf(a1v.z), f2tf(a1v.w));
            *(uint4*)&Bs[nb][lr][lk]      = make_uint4(f2tf(b0v.x), f2tf(b0v.y), f2tf(b0v.z), f2tf(b0v.w));
            *(uint4*)&Bs[nb][lr + 64][lk] = make_uint4(f2tf(b1v.x), f2tf(b1v.y), f2tf(b1v.z), f2tf(b1v.w));
            __syncthreads();
        }
    }

    /* epilogue */
#pragma unroll
    for (int mf = 0; mf < 4; mf++)
#pragma unroll
        for (int i2 = 0; i2 < 2; i2++) {
            int gm = m0 + wm + mf * 16 + g + i2 * 8;
#pragma unroll
            for (int nf = 0; nf < 4; nf++) {
                int gn = n0 + wn + nf * 8 + 2 * tq;
                float v0 = acc[mf][nf][i2 * 2 + 0];
                float v1 = acc[mf][nf][i2 * 2 + 1];
                if (mode == 0) {
                    *(float2*)(C + (size_t)gm * DM + gn) = make_float2(v0, v1);
                } else {
                    int b = gm >> 11, s = gm & (SEQ - 1);
                    int h = gn >> 6,  d = gn & 63;
                    if (mode == 1) {
                        int p = d >> 1;
                        float cc = g_rope[(s * 32 + p) * 2 + 0];
                        float ss = g_rope[(s * 32 + p) * 2 + 1];
                        float e = v0 * cc - v1 * ss;
                        float o = v0 * ss + v1 * cc;
                        v0 = e; v1 = o;
                    }
                    size_t dst = (((size_t)(b * NH + h) * SEQ) + s) * HD + d;
                    *(float2*)(C + dst) = make_float2(v0, v1);
                }
            }
        }
}

/* ------------------------------------------------------------------ */
/* Flash attention on tensor cores (tf32). Block: 128 q-rows, 8 warps  */
/* of 16 rows x 64 keys. Q held in registers as A-fragments.           */
/* ------------------------------------------------------------------ */
#define QS 68   /* Q/K/P smem stride: 68%32=4 -> (4g+tq) bijection     */
#define VST 72  /* V smem stride: 72%32=8 -> (8tq+g) bijection         */
#define FLASH_SMEM ((128 * QS + 64 * QS + 64 * VST) * 4)

__global__ __launch_bounds__(256) void flash_tc(const float* __restrict__ gq,
                                                const float* __restrict__ gk,
                                                const float* __restrict__ gv,
                                                float* __restrict__ gout)
{
    extern __shared__ unsigned sm[];
    unsigned* Ps = sm;                       /* [128][QS]: Q staging, then P */
    unsigned* Ks = sm + 128 * QS;            /* [64][QS]  */
    unsigned* Vs = sm + 128 * QS + 64 * QS;  /* [64][VST] */

    int t = threadIdx.x, lane = t & 31, w = t >> 5;
    int g = lane >> 2, tq = lane & 3;
    int qt = gridDim.x - 1 - blockIdx.x;     /* heavy blocks first */
    int bh = blockIdx.y;

    const float* Qg = gq + ((size_t)bh * SEQ + qt * 128) * HD;

    /* stage Q (tf32) */
    {
        int r = t >> 4, c4 = (t & 15) * 4;
#pragma unroll
        for (int rr = 0; rr < 8; rr++) {
            float4 v = *(const float4*)(Qg + (r + rr * 16) * HD + c4);
            *(uint4*)&Ps[(r + rr * 16) * QS + c4] =
                make_uint4(f2tf(v.x), f2tf(v.y), f2tf(v.z), f2tf(v.w));
        }
    }
    __syncthreads();

    /* Q A-fragments in registers (warp-private rows -> Ps reusable) */
    unsigned qa[8][4];
    int qr = w * 16 + g;
#pragma unroll
    for (int ks = 0; ks < 8; ks++) {
        int k = ks * 8 + tq;
        qa[ks][0] = Ps[qr * QS + k];
        qa[ks][1] = Ps[(qr + 8) * QS + k];
        qa[ks][2] = Ps[qr * QS + k + 4];
        qa[ks][3] = Ps[(qr + 8) * QS + k + 4];
    }

    float o[8][4];
#pragma unroll
    for (int nf = 0; nf < 8; nf++)
#pragma unroll
        for (int i = 0; i < 4; i++) o[nf][i] = 0.0f;
    float m0r = -1e30f, m1r = -1e30f, l0 = 0.0f, l1 = 0.0f;
    const unsigned FULL = 0xffffffffu;

    int nkt = 2 * qt + 2;
    for (int kt = 0; kt < nkt; kt++) {
        __syncthreads();
        {
            const float* Kg = gk + ((size_t)bh * SEQ + kt * 64) * HD;
            const float* Vg = gv + ((size_t)bh * SEQ + kt * 64) * HD;
            int r = t >> 4, c4 = (t & 15) * 4;
#pragma unroll
            for (int rr = 0; rr < 4; rr++) {
                float4 kv = *(const float4*)(Kg + (r + rr * 16) * HD + c4);
                *(uint4*)&Ks[(r + rr * 16) * QS + c4] =
                    make_uint4(f2tf(kv.x), f2tf(kv.y), f2tf(kv.z), f2tf(kv.w));
                float4 vv = *(const float4*)(Vg + (r + rr * 16) * HD + c4);
                *(uint4*)&Vs[(r + rr * 16) * VST + c4] =
                    make_uint4(f2tf(vv.x), f2tf(vv.y), f2tf(vv.z), f2tf(vv.w));
            }
        }
        __syncthreads();

        int gi0 = qt * 128 + w * 16 + g;               /* thread rows gi0, gi0+8 */
        if (kt * 64 > qt * 128 + w * 16 + 15) continue; /* fully masked for warp */

        /* S = Q K^T */
        float s[8][4];
#pragma unroll
        for (int nf = 0; nf < 8; nf++) {
            s[nf][0] = s[nf][1] = s[nf][2] = s[nf][3] = 0.0f;
            int n = nf * 8 + g;
#pragma unroll
            for (int ks = 0; ks < 8; ks++) {
                unsigned b0 = Ks[n * QS + ks * 8 + tq];
                unsigned b1 = Ks[n * QS + ks * 8 + tq + 4];
                mma8(s[nf], qa[ks][0], qa[ks][1], qa[ks][2], qa[ks][3], b0, b1);
            }
        }

        /* scale + causal mask */
        if (kt * 64 + 63 <= gi0) {
#pragma unroll
            for (int nf = 0; nf < 8; nf++)
#pragma unroll
                for (int j = 0; j < 4; j++) s[nf][j] *= 0.125f;
        } else {
#pragma unroll
            for (int nf = 0; nf < 8; nf++)
#pragma unroll
                for (int j = 0; j < 4; j++) {
                    int col = kt * 64 + nf * 8 + 2 * tq + (j & 1);
                    int row = gi0 + (j >> 1) * 8;
                    s[nf][j] = (col > row) ? -1e30f : s[nf][j] * 0.125f;
                }
        }

        /* online softmax (rows qr and qr+8), reduce over quad (xor 1,2) */
        float mt0 = -1e30f, mt1 = -1e30f;
#pragma unroll
        for (int nf = 0; nf < 8; nf++) {
            mt0 = fmaxf(mt0, fmaxf(s[nf][0], s[nf][1]));
            mt1 = fmaxf(mt1, fmaxf(s[nf][2], s[nf][3]));
        }
        mt0 = fmaxf(mt0, __shfl_xor_sync(FULL, mt0, 1));
        mt0 = fmaxf(mt0, __shfl_xor_sync(FULL, mt0, 2));
        mt1 = fmaxf(mt1, __shfl_xor_sync(FULL, mt1, 1));
        mt1 = fmaxf(mt1, __shfl_xor_sync(FULL, mt1, 2));
        float mn0 = fmaxf(m0r, mt0), mn1 = fmaxf(m1r, mt1);
        float al0 = __expf(m0r - mn0), al1 = __expf(m1r - mn1);
        float ps0 = 0.0f, ps1 = 0.0f;
#pragma unroll
        for (int nf = 0; nf < 8; nf++) {
            s[nf][0] = __expf(s[nf][0] - mn0);
            s[nf][1] = __expf(s[nf][1] - mn0);
            s[nf][2] = __expf(s[nf][2] - mn1);
            s[nf][3] = __expf(s[nf][3] - mn1);
            ps0 += s[nf][0] + s[nf][1];
            ps1 += s[nf][2] + s[nf][3];
        }
        ps0 += __shfl_xor_sync(FULL, ps0, 1);
        ps0 += __shfl_xor_sync(FULL, ps0, 2);
        ps1 += __shfl_xor_sync(FULL, ps1, 1);
        ps1 += __shfl_xor_sync(FULL, ps1, 2);
        l0 = l0 * al0 + ps0;  l1 = l1 * al1 + ps1;
        m0r = mn0;  m1r = mn1;
#pragma unroll
        for (int nf = 0; nf < 8; nf++) {
            o[nf][0] *= al0; o[nf][1] *= al0;
            o[nf][2] *= al1; o[nf][3] *= al1;
        }

        /* P -> smem (warp-private rows) */
#pragma unroll
        for (int nf = 0; nf < 8; nf++) {
            *(uint2*)&Ps[qr * QS + nf * 8 + 2 * tq] =
                make_uint2(f2tf(s[nf][0]), f2tf(s[nf][1]));
            *(uint2*)&Ps[(qr + 8) * QS + nf * 8 + 2 * tq] =
                make_uint2(f2tf(s[nf][2]), f2tf(s[nf][3]));
        }
        __syncwarp();

        /* O += P V */
#pragma unroll
        for (int ks = 0; ks < 8; ks++) {
            unsigned pa0 = Ps[qr * QS + ks * 8 + tq];
            unsigned pa1 = Ps[(qr + 8) * QS + ks * 8 + tq];
            unsigned pa2 = Ps[qr * QS + ks * 8 + tq + 4];
            unsigned pa3 = Ps[(qr + 8) * QS + ks * 8 + tq + 4];
#pragma unroll
            for (int nf = 0; nf < 8; nf++) {
                unsigned b0 = Vs[(ks * 8 + tq) * VST + nf * 8 + g];
                unsigned b1 = Vs[(ks * 8 + tq + 4) * VST + nf * 8 + g];
                mma8(o[nf], pa0, pa1, pa2, pa3, b0, b1);
            }
        }
    }

    /* normalize + write [b, s, h*64+d] */
    int b = bh >> 4, h = bh & 15;
    float inv0 = 1.0f / l0, inv1 = 1.0f / l1;
    int s0 = qt * 128 + qr;
#pragma unroll
    for (int nf = 0; nf < 8; nf++) {
        int d = nf * 8 + 2 * tq;
        size_t d0 = ((size_t)b * SEQ + s0) * DM + h * 64 + d;
        size_t d1 = ((size_t)b * SEQ + s0 + 8) * DM + h * 64 + d;
        *(float2*)(gout + d0) = make_float2(o[nf][0] * inv0, o[nf][1] * inv0);
        *(float2*)(gout + d1) = make_float2(o[nf][2] * inv1, o[nf][3] * inv1);
    }
}

/* ------------------------------------------------------------------ */
extern "C" void kernel_launch(void* const* d_in, const int* in_sizes, int n_in,
                              void* d_out, int out_size)
{
    const float* x  = (const float*)d_in[0];
    const float* Wq = (const float*)d_in[1];
    const float* Wk = (const float*)d_in[2];
    const float* Wv = (const float*)d_in[3];
    const float* Wo = (const float*)d_in[4];
    const int*  pos = (const int*)d_in[6];
    float* out = (float*)d_out;

    float *q, *k, *v, *att;
    cudaGetSymbolAddress((void**)&q,   g_q);
    cudaGetSymbolAddress((void**)&k,   g_k);
    cudaGetSymbolAddress((void**)&v,   g_v);
    cudaGetSymbolAddress((void**)&att, g_att);

    cudaFuncSetAttribute(flash_tc, cudaFuncAttributeMaxDynamicSharedMemorySize,
                         FLASH_SMEM);

    rope_fill<<<256, 256>>>(pos);

    dim3 gg(DM / 128, MROWS / 128);  /* (8, 32) */
    gemm_tc<<<gg, 256>>>(x, Wq, q, 1);
    gemm_tc<<<gg, 256>>>(x, Wk, k, 1);
    gemm_tc<<<gg, 256>>>(x, Wv, v, 2);

    flash_tc<<<dim3(SEQ / 128, BATCH * NH), 256, FLASH_SMEM>>>(q, k, v, att);

    gemm_tc<<<gg, 256>>>(att, Wo, out, 0);
}

// round 8
// speedup vs baseline: 5.0834x; 1.7578x over previous
#include <cuda_runtime.h>
#include <cuda_fp16.h>
#include <math.h>
#include <stdint.h>

#define BATCH 2
#define SEQ   2048
#define NH    16
#define HD    64
#define DM    1024
#define MROWS (BATCH*SEQ)   /* 4096 */

/* ------------------------------------------------------------------ */
/* scratch (static device globals)                                     */
/* ------------------------------------------------------------------ */
__device__ __half g_xh [(size_t)MROWS * DM];            /* x fp16 */
__device__ __half g_wqh[(size_t)DM * DM];
__device__ __half g_wkh[(size_t)DM * DM];
__device__ __half g_wvh[(size_t)DM * DM];
__device__ __half g_woh[(size_t)DM * DM];
__device__ __half g_qh [(size_t)BATCH * NH * SEQ * HD]; /* [b,h,s,d] */
__device__ __half g_kh [(size_t)BATCH * NH * SEQ * HD]; /* [b,h,s,d] */
__device__ __half g_vth[(size_t)BATCH * NH * HD * SEQ]; /* [b,h,d,s] */
__device__ __half g_ath[(size_t)MROWS * DM];            /* [b,s,h*d] */
__device__ float  g_rope[SEQ * 32 * 2];

/* ------------------------------------------------------------------ */
/* helpers                                                             */
/* ------------------------------------------------------------------ */
__device__ __forceinline__ uint32_t smem_u32(const void* p)
{
    uint32_t a;
    asm("{ .reg .u64 t; cvta.to.shared.u64 t, %1; cvt.u32.u64 %0, t; }"
        : "=r"(a) : "l"(p));
    return a;
}

__device__ __forceinline__ void cpa16(uint32_t dst, const void* src)
{
    asm volatile("cp.async.cg.shared.global [%0], [%1], 16;" :: "r"(dst), "l"(src));
}
#define CP_COMMIT() asm volatile("cp.async.commit_group;" ::: "memory")
#define CP_WAIT0()  asm volatile("cp.async.wait_group 0;" ::: "memory")
#define CP_WAIT1()  asm volatile("cp.async.wait_group 1;" ::: "memory")
#define CP_WAIT2()  asm volatile("cp.async.wait_group 2;" ::: "memory")

__device__ __forceinline__ void mma16(float* c, uint32_t a0, uint32_t a1,
                                      uint32_t a2, uint32_t a3,
                                      uint32_t b0, uint32_t b1)
{
    asm("mma.sync.aligned.m16n8k16.row.col.f32.f16.f16.f32 "
        "{%0,%1,%2,%3},{%4,%5,%6,%7},{%8,%9},{%0,%1,%2,%3};"
        : "+f"(c[0]), "+f"(c[1]), "+f"(c[2]), "+f"(c[3])
        : "r"(a0), "r"(a1), "r"(a2), "r"(a3), "r"(b0), "r"(b1));
}

/* ------------------------------------------------------------------ */
/* prepass kernels                                                     */
/* ------------------------------------------------------------------ */
__global__ void f2h_k(const float* __restrict__ src, __half* __restrict__ dst, int n4)
{
    int i = blockIdx.x * blockDim.x + threadIdx.x;
    if (i >= n4) return;
    float4 v = ((const float4*)src)[i];
    __half2 h0 = __floats2half2_rn(v.x, v.y);
    __half2 h1 = __floats2half2_rn(v.z, v.w);
    ((uint2*)dst)[i] = make_uint2(*(uint32_t*)&h0, *(uint32_t*)&h1);
}

__global__ void rope_fill(const int* __restrict__ pos)
{
    int idx = blockIdx.x * blockDim.x + threadIdx.x;
    if (idx >= SEQ * 32) return;
    int s = idx >> 5, p = idx & 31;
    float ff  = (float)(1.0 / pow(10000.0, (double)(2 * p) / 64.0));
    float ang = (float)pos[s] * ff;
    double a  = (double)ang;
    g_rope[idx * 2 + 0] = (float)cos(a);
    g_rope[idx * 2 + 1] = (float)sin(a);
}

/* ------------------------------------------------------------------ */
/* fp16 tensor-core GEMM: C = A[4096,1024] @ B[1024,1024]^T            */
/* 128x128 tile, BK=32, 4-stage cp.async. 8 warps of 64x32.            */
/* mode 0: fp32 row-major; 1: fp16 [b,h,s,d]+RoPE; 3: fp16 [b,h,d,s]   */
/* ------------------------------------------------------------------ */
#define GBK   32
#define KSH   40                     /* halfs row stride (80B, 16B-mult) */
#define ABUFH (128 * KSH)            /* 5120 halfs */
#define STGH  (2 * ABUFH)            /* 10240 halfs = 20480 B per stage */
#define NST   4
#define NCH   (DM / GBK)             /* 32 */
#define GSMEM (NST * STGH * 2)       /* 81920 B */

__global__ __launch_bounds__(256, 2) void gemm_h(const __half* __restrict__ A,
                                                 const __half* __restrict__ Bw,
                                                 void* __restrict__ Cp, int mode)
{
    extern __shared__ __half hsm[];
    uint32_t sbase = smem_u32(hsm);

    int t = threadIdx.x, lane = t & 31, w = t >> 5;
    int g = lane >> 2, tq = lane & 3;
    int wm = (w & 1) * 64, wn = (w >> 1) * 32;
    int m0 = blockIdx.y * 128, n0 = blockIdx.x * 128;

    int crow = t >> 2, cq = (t & 3);            /* copy mapping: 2 iters/matrix */

    float acc[4][4][4];
#pragma unroll
    for (int mf = 0; mf < 4; mf++)
#pragma unroll
        for (int nf = 0; nf < 4; nf++)
#pragma unroll
            for (int i = 0; i < 4; i++) acc[mf][nf][i] = 0.0f;

    /* prologue: stages 0..2 */
#pragma unroll
    for (int c = 0; c < 3; c++) {
        uint32_t sa = sbase + c * (STGH * 2);
        uint32_t sbb = sa + ABUFH * 2;
#pragma unroll
        for (int i = 0; i < 2; i++) {
            int row = crow + i * 64;
            cpa16(sa  + row * (KSH * 2) + cq * 16,
                  A  + (size_t)(m0 + row) * DM + c * GBK + cq * 8);
            cpa16(sbb + row * (KSH * 2) + cq * 16,
                  Bw + (size_t)(n0 + row) * DM + c * GBK + cq * 8);
        }
        CP_COMMIT();
    }

#pragma unroll 1
    for (int c = 0; c < NCH; c++) {
        if (c < NCH - 2)      CP_WAIT2();
        else if (c == NCH - 2) CP_WAIT1();
        else                   CP_WAIT0();
        __syncthreads();

        if (c + 3 < NCH) {
            int cn = c + 3, st = cn & 3;
            uint32_t sa = sbase + st * (STGH * 2);
            uint32_t sbb = sa + ABUFH * 2;
#pragma unroll
            for (int i = 0; i < 2; i++) {
                int row = crow + i * 64;
                cpa16(sa  + row * (KSH * 2) + cq * 16,
                      A  + (size_t)(m0 + row) * DM + cn * GBK + cq * 8);
                cpa16(sbb + row * (KSH * 2) + cq * 16,
                      Bw + (size_t)(n0 + row) * DM + cn * GBK + cq * 8);
            }
            CP_COMMIT();
        }

        const __half* sA = hsm + (size_t)(c & 3) * STGH;
        const __half* sB = sA + ABUFH;
#pragma unroll
        for (int ks = 0; ks < 2; ks++) {
            int k16 = ks * 16;
            uint32_t af[4][4], bf[4][2];
#pragma unroll
            for (int mf = 0; mf < 4; mf++) {
                int r = wm + mf * 16 + g;
                af[mf][0] = *(const uint32_t*)&sA[r * KSH + k16 + 2 * tq];
                af[mf][1] = *(const uint32_t*)&sA[(r + 8) * KSH + k16 + 2 * tq];
                af[mf][2] = *(const uint32_t*)&sA[r * KSH + k16 + 8 + 2 * tq];
                af[mf][3] = *(const uint32_t*)&sA[(r + 8) * KSH + k16 + 8 + 2 * tq];
            }
#pragma unroll
            for (int nf = 0; nf < 4; nf++) {
                int n = wn + nf * 8 + g;
                bf[nf][0] = *(const uint32_t*)&sB[n * KSH + k16 + 2 * tq];
                bf[nf][1] = *(const uint32_t*)&sB[n * KSH + k16 + 8 + 2 * tq];
            }
#pragma unroll
            for (int mf = 0; mf < 4; mf++)
#pragma unroll
                for (int nf = 0; nf < 4; nf++)
                    mma16(acc[mf][nf], af[mf][0], af[mf][1], af[mf][2], af[mf][3],
                          bf[nf][0], bf[nf][1]);
        }
    }
    __syncthreads();   /* smem reusable below */

    if (mode == 3) {
        /* V: fp16 transposed [b,h,d,s] via per-warp stage transpose */
        float* stg = (float*)hsm + w * (32 * 33);
        int bb = m0 >> 11;
        int gn = n0 + wn + lane;
        int hh = gn >> 6, dd = gn & 63;
#pragma unroll
        for (int hf = 0; hf < 2; hf++) {
#pragma unroll
            for (int mfl = 0; mfl < 2; mfl++) {
                int mf = hf * 2 + mfl;
                int rl = mfl * 16 + g;
#pragma unroll
                for (int nf = 0; nf < 4; nf++) {
                    int cl = nf * 8 + 2 * tq;
                    stg[rl * 33 + cl]           = acc[mf][nf][0];
                    stg[rl * 33 + cl + 1]       = acc[mf][nf][1];
                    stg[(rl + 8) * 33 + cl]     = acc[mf][nf][2];
                    stg[(rl + 8) * 33 + cl + 1] = acc[mf][nf][3];
                }
            }
            __syncwarp();
            int s0 = (m0 + wm + hf * 32) & (SEQ - 1);
            uint32_t u[16];
#pragma unroll
            for (int i = 0; i < 16; i++) {
                __half2 h = __floats2half2_rn(stg[(2 * i) * 33 + lane],
                                              stg[(2 * i + 1) * 33 + lane]);
                u[i] = *(uint32_t*)&h;
            }
            uint4* dv = (uint4*)((__half*)Cp +
                        ((size_t)(bb * NH + hh) * HD + dd) * SEQ + s0);
            dv[0] = make_uint4(u[0],  u[1],  u[2],  u[3]);
            dv[1] = make_uint4(u[4],  u[5],  u[6],  u[7]);
            dv[2] = make_uint4(u[8],  u[9],  u[10], u[11]);
            dv[3] = make_uint4(u[12], u[13], u[14], u[15]);
            __syncwarp();
        }
        return;
    }

#pragma unroll
    for (int mf = 0; mf < 4; mf++)
#pragma unroll
        for (int i2 = 0; i2 < 2; i2++) {
            int gm = m0 + wm + mf * 16 + g + i2 * 8;
#pragma unroll
            for (int nf = 0; nf < 4; nf++) {
                int gn = n0 + wn + nf * 8 + 2 * tq;
                float v0 = acc[mf][nf][i2 * 2 + 0];
                float v1 = acc[mf][nf][i2 * 2 + 1];
                if (mode == 0) {
                    *(float2*)((float*)Cp + (size_t)gm * DM + gn) = make_float2(v0, v1);
                } else {  /* mode 1: RoPE + fp16 [b,h,s,d] */
                    int bb = gm >> 11, ss = gm & (SEQ - 1);
                    int hh = gn >> 6,  dd = gn & 63;
                    int p = dd >> 1;
                    float cv = g_rope[(ss * 32 + p) * 2 + 0];
                    float sv = g_rope[(ss * 32 + p) * 2 + 1];
                    float e = v0 * cv - v1 * sv;
                    float o = v0 * sv + v1 * cv;
                    __half2 h = __floats2half2_rn(e, o);
                    *(uint32_t*)((__half*)Cp +
                        (((size_t)(bb * NH + hh) * SEQ) + ss) * HD + dd) = *(uint32_t*)&h;
                }
            }
        }
}

/* ------------------------------------------------------------------ */
/* fp16 flash attention. 128 q-rows/block, 8 warps of 16 rows x 64 keys*/
/* K/V double-buffered via cp.async; Q in registers; P reuses Q smem.  */
/* ------------------------------------------------------------------ */
#define FQS 72                      /* halfs stride (144B) */
#define FOFF_K (128 * FQS)
#define FOFF_V (FOFF_K + 2 * 64 * FQS)
#define FSMEM  ((128 * FQS + 4 * 64 * FQS) * 2)   /* 55296 B */

__global__ __launch_bounds__(256) void flash_h(const __half* __restrict__ gq,
                                               const __half* __restrict__ gk,
                                               const __half* __restrict__ gv,
                                               __half* __restrict__ gout)
{
    extern __shared__ __half fsm[];
    uint32_t sbase = smem_u32(fsm);

    int t = threadIdx.x, lane = t & 31, w = t >> 5;
    int g = lane >> 2, tq = lane & 3;
    int qt = gridDim.x - 1 - blockIdx.x;
    int bh = blockIdx.y;
    int qr = w * 16 + g;

    const __half* Qg = gq + ((size_t)bh * SEQ + qt * 128) * HD;
    const __half* Kg = gk + (size_t)bh * SEQ * HD;
    const __half* Vg = gv + (size_t)bh * HD * SEQ;

    /* prologue: Q (128x64) + K/V tile 0, one commit group */
    {
        int row = t >> 1, q8 = (t & 1) * 4;   /* Q: 4 chunks of 16B per row? */
    }
#pragma unroll
    for (int i = 0; i < 4; i++) {             /* Q: 1024 16B-chunks? 128rows*8 */
        int idx = i * 256 + t, row = idx >> 3, q8 = idx & 7;
        cpa16(sbase + row * (FQS * 2) + q8 * 16, Qg + row * HD + q8 * 8);
    }
#pragma unroll
    for (int i = 0; i < 2; i++) {             /* K tile 0: 64 rows x 8 chunks */
        int idx = i * 256 + t, row = idx >> 3, q8 = idx & 7;
        cpa16(sbase + (FOFF_K + row * FQS) * 2 + q8 * 16, Kg + row * HD + q8 * 8);
        cpa16(sbase + (FOFF_V + row * FQS) * 2 + q8 * 16, Vg + (size_t)row * SEQ + q8 * 8);
    }
    CP_COMMIT();

    uint32_t qa[4][4];
    float o[8][4];
#pragma unroll
    for (int nf = 0; nf < 8; nf++)
#pragma unroll
        for (int i = 0; i < 4; i++) o[nf][i] = 0.0f;
    float m0r = -1e30f, m1r = -1e30f, l0 = 0.0f, l1 = 0.0f;
    const unsigned FULL = 0xffffffffu;

    int nkt = 2 * qt + 2;
#pragma unroll 1
    for (int kt = 0; kt < nkt; kt++) {
        CP_WAIT0();
        __syncthreads();

        if (kt + 1 < nkt) {
            int nb = (kt + 1) & 1;
            const __half* Kn = Kg + (size_t)(kt + 1) * 64 * HD;
#pragma unroll
            for (int i = 0; i < 2; i++) {
                int idx = i * 256 + t, row = idx >> 3, q8 = idx & 7;
                cpa16(sbase + (FOFF_K + (nb * 64 + row) * FQS) * 2 + q8 * 16,
                      Kn + row * HD + q8 * 8);
                cpa16(sbase + (FOFF_V + (nb * 64 + row) * FQS) * 2 + q8 * 16,
                      Vg + (size_t)row * SEQ + (kt + 1) * 64 + q8 * 8);
            }
            CP_COMMIT();
        }

        if (kt == 0) {
#pragma unroll
            for (int ks = 0; ks < 4; ks++) {
                qa[ks][0] = *(const uint32_t*)&fsm[qr * FQS + ks * 16 + 2 * tq];
                qa[ks][1] = *(const uint32_t*)&fsm[(qr + 8) * FQS + ks * 16 + 2 * tq];
                qa[ks][2] = *(const uint32_t*)&fsm[qr * FQS + ks * 16 + 8 + 2 * tq];
                qa[ks][3] = *(const uint32_t*)&fsm[(qr + 8) * FQS + ks * 16 + 8 + 2 * tq];
            }
        }

        if (kt * 64 > qt * 128 + w * 16 + 15) continue;  /* fully masked warp */

        const __half* Ksp = fsm + FOFF_K + (kt & 1) * 64 * FQS;
        const __half* Vsp = fsm + FOFF_V + (kt & 1) * 64 * FQS;

        /* S = Q K^T */
        float s[8][4];
#pragma unroll
        for (int nf = 0; nf < 8; nf++) {
            s[nf][0] = s[nf][1] = s[nf][2] = s[nf][3] = 0.0f;
            int n = nf * 8 + g;
#pragma unroll
            for (int ks = 0; ks < 4; ks++) {
                uint32_t b0 = *(const uint32_t*)&Ksp[n * FQS + ks * 16 + 2 * tq];
                uint32_t b1 = *(const uint32_t*)&Ksp[n * FQS + ks * 16 + 8 + 2 * tq];
                mma16(s[nf], qa[ks][0], qa[ks][1], qa[ks][2], qa[ks][3], b0, b1);
            }
        }

        int gi0 = qt * 128 + w * 16 + g;
        if (kt * 64 + 63 <= gi0) {
#pragma unroll
            for (int nf = 0; nf < 8; nf++)
#pragma unroll
                for (int j = 0; j < 4; j++) s[nf][j] *= 0.125f;
        } else {
#pragma unroll
            for (int nf = 0; nf < 8; nf++)
#pragma unroll
                for (int j = 0; j < 4; j++) {
                    int col = kt * 64 + nf * 8 + 2 * tq + (j & 1);
                    int row = gi0 + (j >> 1) * 8;
                    s[nf][j] = (col > row) ? -1e30f : s[nf][j] * 0.125f;
                }
        }

        /* online softmax */
        float mt0 = -1e30f, mt1 = -1e30f;
#pragma unroll
        for (int nf = 0; nf < 8; nf++) {
            mt0 = fmaxf(mt0, fmaxf(s[nf][0], s[nf][1]));
            mt1 = fmaxf(mt1, fmaxf(s[nf][2], s[nf][3]));
        }
        mt0 = fmaxf(mt0, __shfl_xor_sync(FULL, mt0, 1));
        mt0 = fmaxf(mt0, __shfl_xor_sync(FULL, mt0, 2));
        mt1 = fmaxf(mt1, __shfl_xor_sync(FULL, mt1, 1));
        mt1 = fmaxf(mt1, __shfl_xor_sync(FULL, mt1, 2));
        float mn0 = fmaxf(m0r, mt0), mn1 = fmaxf(m1r, mt1);
        float al0 = __expf(m0r - mn0), al1 = __expf(m1r - mn1);
        float ps0 = 0.0f, ps1 = 0.0f;
#pragma unroll
        for (int nf = 0; nf < 8; nf++) {
            s[nf][0] = __expf(s[nf][0] - mn0);
            s[nf][1] = __expf(s[nf][1] - mn0);
            s[nf][2] = __expf(s[nf][2] - mn1);
            s[nf][3] = __expf(s[nf][3] - mn1);
            ps0 += s[nf][0] + s[nf][1];
            ps1 += s[nf][2] + s[nf][3];
        }
        ps0 += __shfl_xor_sync(FULL, ps0, 1);
        ps0 += __shfl_xor_sync(FULL, ps0, 2);
        ps1 += __shfl_xor_sync(FULL, ps1, 1);
        ps1 += __shfl_xor_sync(FULL, ps1, 2);
        l0 = l0 * al0 + ps0;  l1 = l1 * al1 + ps1;
        m0r = mn0;  m1r = mn1;
#pragma unroll
        for (int nf = 0; nf < 8; nf++) {
            o[nf][0] *= al0; o[nf][1] *= al0;
            o[nf][2] *= al1; o[nf][3] *= al1;
        }

        /* P -> fp16 smem (reuse Q region; warp-private rows) */
#pragma unroll
        for (int nf = 0; nf < 8; nf++) {
            __half2 h0 = __floats2half2_rn(s[nf][0], s[nf][1]);
            __half2 h1 = __floats2half2_rn(s[nf][2], s[nf][3]);
            *(uint32_t*)&fsm[qr * FQS + nf * 8 + 2 * tq]       = *(uint32_t*)&h0;
            *(uint32_t*)&fsm[(qr + 8) * FQS + nf * 8 + 2 * tq] = *(uint32_t*)&h1;
        }
        __syncwarp();

        /* O += P V */
#pragma unroll
        for (int ks = 0; ks < 4; ks++) {
            uint32_t pa0 = *(const uint32_t*)&fsm[qr * FQS + ks * 16 + 2 * tq];
            uint32_t pa1 = *(const uint32_t*)&fsm[(qr + 8) * FQS + ks * 16 + 2 * tq];
            uint32_t pa2 = *(const uint32_t*)&fsm[qr * FQS + ks * 16 + 8 + 2 * tq];
            uint32_t pa3 = *(const uint32_t*)&fsm[(qr + 8) * FQS + ks * 16 + 8 + 2 * tq];
#pragma unroll
            for (int nf = 0; nf < 8; nf++) {
                int n = nf * 8 + g;
                uint32_t b0 = *(const uint32_t*)&Vsp[n * FQS + ks * 16 + 2 * tq];
                uint32_t b1 = *(const uint32_t*)&Vsp[n * FQS + ks * 16 + 8 + 2 * tq];
                mma16(o[nf], pa0, pa1, pa2, pa3, b0, b1);
            }
        }
    }

    /* normalize + write fp16 att [b, s, h*64+d] */
    int b = bh >> 4, h = bh & 15;
    float inv0 = 1.0f / l0, inv1 = 1.0f / l1;
    int s0 = qt * 128 + qr;
#pragma unroll
    for (int nf = 0; nf < 8; nf++) {
        int d = nf * 8 + 2 * tq;
        __half2 h0 = __floats2half2_rn(o[nf][0] * inv0, o[nf][1] * inv0);
        __half2 h1 = __floats2half2_rn(o[nf][2] * inv1, o[nf][3] * inv1);
        *(uint32_t*)(gout + ((size_t)b * SEQ + s0) * DM + h * 64 + d)     = *(uint32_t*)&h0;
        *(uint32_t*)(gout + ((size_t)b * SEQ + s0 + 8) * DM + h * 64 + d) = *(uint32_t*)&h1;
    }
}

/* ------------------------------------------------------------------ */
extern "C" void kernel_launch(void* const* d_in, const int* in_sizes, int n_in,
                              void* d_out, int out_size)
{
    const float* x  = (const float*)d_in[0];
    const float* Wq = (const float*)d_in[1];
    const float* Wk = (const float*)d_in[2];
    const float* Wv = (const float*)d_in[3];
    const float* Wo = (const float*)d_in[4];
    const int*  pos = (const int*)d_in[6];
    float* out = (float*)d_out;

    __half *xh, *wqh, *wkh, *wvh, *woh, *qh, *kh, *vth, *ath;
    cudaGetSymbolAddress((void**)&xh,  g_xh);
    cudaGetSymbolAddress((void**)&wqh, g_wqh);
    cudaGetSymbolAddress((void**)&wkh, g_wkh);
    cudaGetSymbolAddress((void**)&wvh, g_wvh);
    cudaGetSymbolAddress((void**)&woh, g_woh);
    cudaGetSymbolAddress((void**)&qh,  g_qh);
    cudaGetSymbolAddress((void**)&kh,  g_kh);
    cudaGetSymbolAddress((void**)&vth, g_vth);
    cudaGetSymbolAddress((void**)&ath, g_ath);

    cudaFuncSetAttribute(gemm_h,  cudaFuncAttributeMaxDynamicSharedMemorySize, GSMEM);
    cudaFuncSetAttribute(flash_h, cudaFuncAttributeMaxDynamicSharedMemorySize, FSMEM);

    /* prepass: fp32 -> fp16 + rope table */
    int nx4 = MROWS * DM / 4, nw4 = DM * DM / 4;
    f2h_k<<<(nx4 + 255) / 256, 256>>>(x,  xh,  nx4);
    f2h_k<<<(nw4 + 255) / 256, 256>>>(Wq, wqh, nw4);
    f2h_k<<<(nw4 + 255) / 256, 256>>>(Wk, wkh, nw4);
    f2h_k<<<(nw4 + 255) / 256, 256>>>(Wv, wvh, nw4);
    f2h_k<<<(nw4 + 255) / 256, 256>>>(Wo, woh, nw4);
    rope_fill<<<256, 256>>>(pos);

    dim3 gg(DM / 128, MROWS / 128);   /* (8, 32) */
    gemm_h<<<gg, 256, GSMEM>>>(xh, wqh, qh,  1);
    gemm_h<<<gg, 256, GSMEM>>>(xh, wkh, kh,  1);
    gemm_h<<<gg, 256, GSMEM>>>(xh, wvh, vth, 3);

    flash_h<<<dim3(SEQ / 128, BATCH * NH), 256, FSMEM>>>(qh, kh, vth, ath);

    gemm_h<<<gg, 256, GSMEM>>>(ath, woh, out, 0);
}

// round 10
// speedup vs baseline: 5.8992x; 1.1605x over previous
#include <cuda_runtime.h>
#include <cuda_fp16.h>
#include <math.h>
#include <stdint.h>

#define BATCH 2
#define SEQ   2048
#define NH    16
#define HD    64
#define DM    1024
#define MROWS (BATCH*SEQ)   /* 4096 */

/* ------------------------------------------------------------------ */
/* scratch                                                             */
/* ------------------------------------------------------------------ */
__device__ __half g_xh [(size_t)MROWS * DM];
__device__ __half g_wqh[(size_t)DM * DM];
__device__ __half g_wkh[(size_t)DM * DM];
__device__ __half g_wvh[(size_t)DM * DM];
__device__ __half g_woh[(size_t)DM * DM];
__device__ __half g_qh [(size_t)BATCH * NH * SEQ * HD]; /* [b,h,s,d] */
__device__ __half g_kh [(size_t)BATCH * NH * SEQ * HD]; /* [b,h,s,d] */
__device__ __half g_vth[(size_t)BATCH * NH * HD * SEQ]; /* [b,h,d,s] */
__device__ __half g_ath[(size_t)MROWS * DM];            /* [b,s,h*d] */
__device__ float  g_rope[SEQ * 32 * 2];

/* ------------------------------------------------------------------ */
/* helpers                                                             */
/* ------------------------------------------------------------------ */
__device__ __forceinline__ uint32_t smem_u32(const void* p)
{
    uint32_t a;
    asm("{ .reg .u64 t; cvta.to.shared.u64 t, %1; cvt.u32.u64 %0, t; }"
        : "=r"(a) : "l"(p));
    return a;
}

__device__ __forceinline__ void cpa16(uint32_t dst, const void* src)
{
    asm volatile("cp.async.cg.shared.global [%0], [%1], 16;" :: "r"(dst), "l"(src));
}
#define CP_COMMIT() asm volatile("cp.async.commit_group;" ::: "memory")
#define CP_WAIT0()  asm volatile("cp.async.wait_group 0;" ::: "memory")
#define CP_WAIT1()  asm volatile("cp.async.wait_group 1;" ::: "memory")
#define CP_WAIT2()  asm volatile("cp.async.wait_group 2;" ::: "memory")

__device__ __forceinline__ void mma16(float* c, uint32_t a0, uint32_t a1,
                                      uint32_t a2, uint32_t a3,
                                      uint32_t b0, uint32_t b1)
{
    asm("mma.sync.aligned.m16n8k16.row.col.f32.f16.f16.f32 "
        "{%0,%1,%2,%3},{%4,%5,%6,%7},{%8,%9},{%0,%1,%2,%3};"
        : "+f"(c[0]), "+f"(c[1]), "+f"(c[2]), "+f"(c[3])
        : "r"(a0), "r"(a1), "r"(a2), "r"(a3), "r"(b0), "r"(b1));
}

__device__ __forceinline__ void ldm4(uint32_t* r, uint32_t addr)
{
    asm volatile("ldmatrix.sync.aligned.m8n8.x4.shared.b16 {%0,%1,%2,%3}, [%4];"
        : "=r"(r[0]), "=r"(r[1]), "=r"(r[2]), "=r"(r[3]) : "r"(addr));
}

__device__ __forceinline__ uint32_t h2pack(float a, float b)
{
    __half2 h = __floats2half2_rn(a, b);
    return *(uint32_t*)&h;
}

/* ------------------------------------------------------------------ */
/* prepass                                                             */
/* ------------------------------------------------------------------ */
__global__ void f2h_k(const float* __restrict__ src, __half* __restrict__ dst, int n4)
{
    int i = blockIdx.x * blockDim.x + threadIdx.x;
    if (i >= n4) return;
    float4 v = ((const float4*)src)[i];
    ((uint2*)dst)[i] = make_uint2(h2pack(v.x, v.y), h2pack(v.z, v.w));
}

__global__ void f2h4_k(const float* s0, const float* s1, const float* s2,
                       const float* s3, __half* d0, __half* d1, __half* d2,
                       __half* d3, int n4)
{
    int i = blockIdx.x * blockDim.x + threadIdx.x;
    if (i >= n4) return;
    const float* s; __half* d;
    switch (blockIdx.y) {
        case 0: s = s0; d = d0; break;
        case 1: s = s1; d = d1; break;
        case 2: s = s2; d = d2; break;
        default: s = s3; d = d3; break;
    }
    float4 v = ((const float4*)s)[i];
    ((uint2*)d)[i] = make_uint2(h2pack(v.x, v.y), h2pack(v.z, v.w));
}

__global__ void rope_fill(const int* __restrict__ pos)
{
    int idx = blockIdx.x * blockDim.x + threadIdx.x;
    if (idx >= SEQ * 32) return;
    int s = idx >> 5, p = idx & 31;
    float ff  = (float)(1.0 / pow(10000.0, (double)(2 * p) / 64.0));
    float ang = (float)pos[s] * ff;
    double a  = (double)ang;
    g_rope[idx * 2 + 0] = (float)cos(a);
    g_rope[idx * 2 + 1] = (float)sin(a);
}

/* ------------------------------------------------------------------ */
/* fp16 GEMM, ldmatrix fragments. 128x128 tile, BK=32, 4-stage cp.async*/
/* mode 0: fp32 row-major; 1: fp16 [b,h,s,d]+RoPE; 3: fp16 [b,h,d,s]   */
/* qkv kernel: gridDim.z selects (Wq,1) (Wk,1) (Wv,3).                 */
/* ------------------------------------------------------------------ */
#define GBK   32
#define KSH   40
#define ABUFH (128 * KSH)
#define STGH  (2 * ABUFH)
#define NST   4
#define NCH   (DM / GBK)
#define GSMEM (NST * STGH * 2)

__device__ __forceinline__ void gemm_body(const __half* __restrict__ A,
                                          const __half* __restrict__ Bw,
                                          void* __restrict__ Cp, int mode,
                                          __half* hsm, int m0, int n0)
{
    uint32_t sbase = smem_u32(hsm);
    int t = threadIdx.x, lane = t & 31, w = t >> 5;
    int g = lane >> 2, tq = lane & 3;
    int wm = (w & 1) * 64, wn = (w >> 1) * 32;
    int crow = t >> 2, cq = (t & 3);

    float acc[4][4][4];
#pragma unroll
    for (int mf = 0; mf < 4; mf++)
#pragma unroll
        for (int nf = 0; nf < 4; nf++)
#pragma unroll
            for (int i = 0; i < 4; i++) acc[mf][nf][i] = 0.0f;

    /* ldmatrix per-lane byte offsets */
    int arow = (lane & 7) + ((lane >> 3) & 1) * 8;
    int akoff = (lane >> 4) * 8;
    int brow = (lane & 7) + ((lane >> 4) & 1) * 8;
    int bkoff = ((lane >> 3) & 1) * 8;
    uint32_t a_off[4], b_off[2];
#pragma unroll
    for (int mf = 0; mf < 4; mf++)
        a_off[mf] = ((wm + mf * 16 + arow) * KSH + akoff) * 2;
#pragma unroll
    for (int p = 0; p < 2; p++)
        b_off[p] = ((wn + p * 16 + brow) * KSH + bkoff) * 2 + ABUFH * 2;

#pragma unroll
    for (int c = 0; c < 3; c++) {
        uint32_t sa = sbase + c * (STGH * 2);
        uint32_t sbb = sa + ABUFH * 2;
#pragma unroll
        for (int i = 0; i < 2; i++) {
            int row = crow + i * 64;
            cpa16(sa  + row * (KSH * 2) + cq * 16,
                  A  + (size_t)(m0 + row) * DM + c * GBK + cq * 8);
            cpa16(sbb + row * (KSH * 2) + cq * 16,
                  Bw + (size_t)(n0 + row) * DM + c * GBK + cq * 8);
        }
        CP_COMMIT();
    }

#pragma unroll 1
    for (int c = 0; c < NCH; c++) {
        if (c < NCH - 2)       CP_WAIT2();
        else if (c == NCH - 2) CP_WAIT1();
        else                   CP_WAIT0();
        __syncthreads();

        if (c + 3 < NCH) {
            int cn = c + 3, st = cn & 3;
            uint32_t sa = sbase + st * (STGH * 2);
            uint32_t sbb = sa + ABUFH * 2;
#pragma unroll
            for (int i = 0; i < 2; i++) {
                int row = crow + i * 64;
                cpa16(sa  + row * (KSH * 2) + cq * 16,
                      A  + (size_t)(m0 + row) * DM + cn * GBK + cq * 8);
                cpa16(sbb + row * (KSH * 2) + cq * 16,
                      Bw + (size_t)(n0 + row) * DM + cn * GBK + cq * 8);
            }
            CP_COMMIT();
        }

        uint32_t stb = sbase + (uint32_t)(c & 3) * (STGH * 2);
#pragma unroll
        for (int ks = 0; ks < 2; ks++) {
            uint32_t kb = ks * 32;   /* 16 halfs */
            uint32_t af[4][4], bf[2][4];
#pragma unroll
            for (int mf = 0; mf < 4; mf++) ldm4(af[mf], stb + a_off[mf] + kb);
#pragma unroll
            for (int p = 0; p < 2; p++)    ldm4(bf[p], stb + b_off[p] + kb);
#pragma unroll
            for (int mf = 0; mf < 4; mf++)
#pragma unroll
                for (int nf = 0; nf < 4; nf++)
                    mma16(acc[mf][nf], af[mf][0], af[mf][1], af[mf][2], af[mf][3],
                          bf[nf >> 1][(nf & 1) * 2], bf[nf >> 1][(nf & 1) * 2 + 1]);
        }
    }
    __syncthreads();

    if (mode == 3) {
        float* stg = (float*)hsm + w * (32 * 33);
        int bb = m0 >> 11;
        int gn = n0 + wn + lane;
        int hh = gn >> 6, dd = gn & 63;
#pragma unroll
        for (int hf = 0; hf < 2; hf++) {
#pragma unroll
            for (int mfl = 0; mfl < 2; mfl++) {
                int mf = hf * 2 + mfl;
                int rl = mfl * 16 + g;
#pragma unroll
                for (int nf = 0; nf < 4; nf++) {
                    int cl = nf * 8 + 2 * tq;
                    stg[rl * 33 + cl]           = acc[mf][nf][0];
                    stg[rl * 33 + cl + 1]       = acc[mf][nf][1];
                    stg[(rl + 8) * 33 + cl]     = acc[mf][nf][2];
                    stg[(rl + 8) * 33 + cl + 1] = acc[mf][nf][3];
                }
            }
            __syncwarp();
            int s0 = (m0 + wm + hf * 32) & (SEQ - 1);
            uint32_t u[16];
#pragma unroll
            for (int i = 0; i < 16; i++)
                u[i] = h2pack(stg[(2 * i) * 33 + lane], stg[(2 * i + 1) * 33 + lane]);
            uint4* dv = (uint4*)((__half*)Cp +
                        ((size_t)(bb * NH + hh) * HD + dd) * SEQ + s0);
            dv[0] = make_uint4(u[0],  u[1],  u[2],  u[3]);
            dv[1] = make_uint4(u[4],  u[5],  u[6],  u[7]);
            dv[2] = make_uint4(u[8],  u[9],  u[10], u[11]);
            dv[3] = make_uint4(u[12], u[13], u[14], u[15]);
            __syncwarp();
        }
        return;
    }

#pragma unroll
    for (int mf = 0; mf < 4; mf++)
#pragma unroll
        for (int i2 = 0; i2 < 2; i2++) {
            int gm = m0 + wm + mf * 16 + g + i2 * 8;
#pragma unroll
            for (int nf = 0; nf < 4; nf++) {
                int gn = n0 + wn + nf * 8 + 2 * tq;
                float v0 = acc[mf][nf][i2 * 2 + 0];
                float v1 = acc[mf][nf][i2 * 2 + 1];
                if (mode == 0) {
                    *(float2*)((float*)Cp + (size_t)gm * DM + gn) = make_float2(v0, v1);
                } else {
                    int bb = gm >> 11, ss = gm & (SEQ - 1);
                    int hh = gn >> 6,  dd = gn & 63;
                    int p = dd >> 1;
                    float cv = g_rope[(ss * 32 + p) * 2 + 0];
                    float sv = g_rope[(ss * 32 + p) * 2 + 1];
                    uint32_t h = h2pack(v0 * cv - v1 * sv, v0 * sv + v1 * cv);
                    *(uint32_t*)((__half*)Cp +
                        (((size_t)(bb * NH + hh) * SEQ) + ss) * HD + dd) = h;
                }
            }
        }
}

__global__ __launch_bounds__(256, 2) void gemm_qkv(const __half* __restrict__ xh,
    const __half* __restrict__ wq, const __half* __restrict__ wk,
    const __half* __restrict__ wv, __half* __restrict__ qh,
    __half* __restrict__ kh, __half* __restrict__ vth)
{
    extern __shared__ __half hsm[];
    const __half* Bw; void* Cp; int mode;
    if (blockIdx.z == 0)      { Bw = wq; Cp = qh;  mode = 1; }
    else if (blockIdx.z == 1) { Bw = wk; Cp = kh;  mode = 1; }
    else                      { Bw = wv; Cp = vth; mode = 3; }
    gemm_body(xh, Bw, Cp, mode, hsm, blockIdx.y * 128, blockIdx.x * 128);
}

__global__ __launch_bounds__(256, 2) void gemm_out(const __half* __restrict__ A,
    const __half* __restrict__ Bw, float* __restrict__ C)
{
    extern __shared__ __half hsm[];
    gemm_body(A, Bw, C, 0, hsm, blockIdx.y * 128, blockIdx.x * 128);
}

/* ------------------------------------------------------------------ */
/* fp16 flash. 128 q/block, 8 warps x (16 rows x 64 keys). ldmatrix    */
/* K/V/Q fragments; P kept in registers (S layout == PV A-fragment).   */
/* ------------------------------------------------------------------ */
#define FQS 72
#define FOFF_K (128 * FQS)
#define FOFF_V (FOFF_K + 2 * 64 * FQS)
#define FSMEM  ((128 * FQS + 4 * 64 * FQS) * 2)

__global__ __launch_bounds__(256) void flash_h(const __half* __restrict__ gq,
                                               const __half* __restrict__ gk,
                                               const __half* __restrict__ gv,
                                               __half* __restrict__ gout)
{
    extern __shared__ __half fsm[];
    uint32_t sbase = smem_u32(fsm);

    int t = threadIdx.x, lane = t & 31, w = t >> 5;
    int g = lane >> 2, tq = lane & 3;
    int qt = gridDim.x - 1 - blockIdx.x;
    int bh = blockIdx.y;
    int qr = w * 16 + g;

    const __half* Qg = gq + ((size_t)bh * SEQ + qt * 128) * HD;
    const __half* Kg = gk + (size_t)bh * SEQ * HD;
    const __half* Vg = gv + (size_t)bh * HD * SEQ;

#pragma unroll
    for (int i = 0; i < 4; i++) {
        int idx = i * 256 + t, row = idx >> 3, q8 = idx & 7;
        cpa16(sbase + row * (FQS * 2) + q8 * 16, Qg + row * HD + q8 * 8);
    }
#pragma unroll
    for (int i = 0; i < 2; i++) {
        int idx = i * 256 + t, row = idx >> 3, q8 = idx & 7;
        cpa16(sbase + (FOFF_K + row * FQS) * 2 + q8 * 16, Kg + row * HD + q8 * 8);
        cpa16(sbase + (FOFF_V + row * FQS) * 2 + q8 * 16, Vg + (size_t)row * SEQ + q8 * 8);
    }
    CP_COMMIT();

    /* ldmatrix per-lane offsets */
    int arow = (lane & 7) + ((lane >> 3) & 1) * 8;
    int akoff = (lane >> 4) * 8;
    int brow = (lane & 7) + ((lane >> 4) & 1) * 8;
    int bkoff = ((lane >> 3) & 1) * 8;
    uint32_t q_off = ((w * 16 + arow) * FQS + akoff) * 2;
    uint32_t kv_off[4];
#pragma unroll
    for (int p = 0; p < 4; p++)
        kv_off[p] = ((p * 16 + brow) * FQS + bkoff) * 2;

    uint32_t qa[4][4];
    float o[8][4];
#pragma unroll
    for (int nf = 0; nf < 8; nf++)
#pragma unroll
        for (int i = 0; i < 4; i++) o[nf][i] = 0.0f;
    float m0r = -1e30f, m1r = -1e30f, l0 = 0.0f, l1 = 0.0f;
    const unsigned FULL = 0xffffffffu;

    int nkt = 2 * qt + 2;
#pragma unroll 1
    for (int kt = 0; kt < nkt; kt++) {
        CP_WAIT0();
        __syncthreads();

        if (kt + 1 < nkt) {
            int nb = (kt + 1) & 1;
            const __half* Kn = Kg + (size_t)(kt + 1) * 64 * HD;
#pragma unroll
            for (int i = 0; i < 2; i++) {
                int idx = i * 256 + t, row = idx >> 3, q8 = idx & 7;
                cpa16(sbase + (FOFF_K + (nb * 64 + row) * FQS) * 2 + q8 * 16,
                      Kn + row * HD + q8 * 8);
                cpa16(sbase + (FOFF_V + (nb * 64 + row) * FQS) * 2 + q8 * 16,
                      Vg + (size_t)row * SEQ + (kt + 1) * 64 + q8 * 8);
            }
            CP_COMMIT();
        }

        if (kt == 0) {
#pragma unroll
            for (int ks = 0; ks < 4; ks++) ldm4(qa[ks], sbase + q_off + ks * 32);
        }

        if (kt * 64 > qt * 128 + w * 16 + 15) continue;

        uint32_t kbase = sbase + (FOFF_K + (kt & 1) * 64 * FQS) * 2;
        uint32_t vbase = sbase + (FOFF_V + (kt & 1) * 64 * FQS) * 2;

        /* S = Q K^T */
        float s[8][4];
#pragma unroll
        for (int nf = 0; nf < 8; nf++)
            s[nf][0] = s[nf][1] = s[nf][2] = s[nf][3] = 0.0f;
#pragma unroll
        for (int ks = 0; ks < 4; ks++) {
            uint32_t kr[4][4];
#pragma unroll
            for (int p = 0; p < 4; p++) ldm4(kr[p], kbase + kv_off[p] + ks * 32);
#pragma unroll
            for (int nf = 0; nf < 8; nf++)
                mma16(s[nf], qa[ks][0], qa[ks][1], qa[ks][2], qa[ks][3],
                      kr[nf >> 1][(nf & 1) * 2], kr[nf >> 1][(nf & 1) * 2 + 1]);
        }

        int gi0 = qt * 128 + w * 16 + g;
        if (kt * 64 + 63 <= gi0) {
#pragma unroll
            for (int nf = 0; nf < 8; nf++)
#pragma unroll
                for (int j = 0; j < 4; j++) s[nf][j] *= 0.125f;
        } else {
#pragma unroll
            for (int nf = 0; nf < 8; nf++)
#pragma unroll
                for (int j = 0; j < 4; j++) {
                    int col = kt * 64 + nf * 8 + 2 * tq + (j & 1);
                    int row = gi0 + (j >> 1) * 8;
                    s[nf][j] = (col > row) ? -1e30f : s[nf][j] * 0.125f;
                }
        }

        /* online softmax */
        float mt0 = -1e30f, mt1 = -1e30f;
#pragma unroll
        for (int nf = 0; nf < 8; nf++) {
            mt0 = fmaxf(mt0, fmaxf(s[nf][0], s[nf][1]));
            mt1 = fmaxf(mt1, fmaxf(s[nf][2], s[nf][3]));
        }
        mt0 = fmaxf(mt0, __shfl_xor_sync(FULL, mt0, 1));
        mt0 = fmaxf(mt0, __shfl_xor_sync(FULL, mt0, 2));
        mt1 = fmaxf(mt1, __shfl_xor_sync(FULL, mt1, 1));
        mt1 = fmaxf(mt1, __shfl_xor_sync(FULL, mt1, 2));
        float mn0 = fmaxf(m0r, mt0), mn1 = fmaxf(m1r, mt1);
        float al0 = __expf(m0r - mn0), al1 = __expf(m1r - mn1);
        float ps0 = 0.0f, ps1 = 0.0f;
#pragma unroll
        for (int nf = 0; nf < 8; nf++) {
            s[nf][0] = __expf(s[nf][0] - mn0);
            s[nf][1] = __expf(s[nf][1] - mn0);
            s[nf][2] = __expf(s[nf][2] - mn1);
            s[nf][3] = __expf(s[nf][3] - mn1);
            ps0 += s[nf][0] + s[nf][1];
            ps1 += s[nf][2] + s[nf][3];
        }
        ps0 += __shfl_xor_sync(FULL, ps0, 1);
        ps0 += __shfl_xor_sync(FULL, ps0, 2);
        ps1 += __shfl_xor_sync(FULL, ps1, 1);
        ps1 += __shfl_xor_sync(FULL, ps1, 2);
        l0 = l0 * al0 + ps0;  l1 = l1 * al1 + ps1;
        m0r = mn0;  m1r = mn1;
#pragma unroll
        for (int nf = 0; nf < 8; nf++) {
            o[nf][0] *= al0; o[nf][1] *= al0;
            o[nf][2] *= al1; o[nf][3] *= al1;
        }

        /* O += P V : P directly from s-registers (A-fragment layout) */
#pragma unroll
        for (int ks = 0; ks < 4; ks++) {
            uint32_t pa0 = h2pack(s[2 * ks][0],     s[2 * ks][1]);
            uint32_t pa1 = h2pack(s[2 * ks][2],     s[2 * ks][3]);
            uint32_t pa2 = h2pack(s[2 * ks + 1][0], s[2 * ks + 1][1]);
            uint32_t pa3 = h2pack(s[2 * ks + 1][2], s[2 * ks + 1][3]);
            uint32_t vr[4][4];
#pragma unroll
            for (int p = 0; p < 4; p++) ldm4(vr[p], vbase + kv_off[p] + ks * 32);
#pragma unroll
            for (int nf = 0; nf < 8; nf++)
                mma16(o[nf], pa0, pa1, pa2, pa3,
                      vr[nf >> 1][(nf & 1) * 2], vr[nf >> 1][(nf & 1) * 2 + 1]);
        }
    }

    /* normalize + write fp16 att */
    int b = bh >> 4, h = bh & 15;
    float inv0 = 1.0f / l0, inv1 = 1.0f / l1;
    int s0 = qt * 128 + qr;
#pragma unroll
    for (int nf = 0; nf < 8; nf++) {
        int d = nf * 8 + 2 * tq;
        *(uint32_t*)(gout + ((size_t)b * SEQ + s0) * DM + h * 64 + d) =
            h2pack(o[nf][0] * inv0, o[nf][1] * inv0);
        *(uint32_t*)(gout + ((size_t)b * SEQ + s0 + 8) * DM + h * 64 + d) =
            h2pack(o[nf][2] * inv1, o[nf][3] * inv1);
    }
}

/* ------------------------------------------------------------------ */
extern "C" void kernel_launch(void* const* d_in, const int* in_sizes, int n_in,
                              void* d_out, int out_size)
{
    const float* x  = (const float*)d_in[0];
    const float* Wq = (const float*)d_in[1];
    const float* Wk = (const float*)d_in[2];
    const float* Wv = (const float*)d_in[3];
    const float* Wo = (const float*)d_in[4];
    const int*  pos = (const int*)d_in[6];
    float* out = (float*)d_out;

    __half *xh, *wqh, *wkh, *wvh, *woh, *qh, *kh, *vth, *ath;
    cudaGetSymbolAddress((void**)&xh,  g_xh);
    cudaGetSymbolAddress((void**)&wqh, g_wqh);
    cudaGetSymbolAddress((void**)&wkh, g_wkh);
    cudaGetSymbolAddress((void**)&wvh, g_wvh);
    cudaGetSymbolAddress((void**)&woh, g_woh);
    cudaGetSymbolAddress((void**)&qh,  g_qh);
    cudaGetSymbolAddress((void**)&kh,  g_kh);
    cudaGetSymbolAddress((void**)&vth, g_vth);
    cudaGetSymbolAddress((void**)&ath, g_ath);

    cudaFuncSetAttribute(gemm_qkv, cudaFuncAttributeMaxDynamicSharedMemorySize, GSMEM);
    cudaFuncSetAttribute(gemm_out, cudaFuncAttributeMaxDynamicSharedMemorySize, GSMEM);
    cudaFuncSetAttribute(flash_h,  cudaFuncAttributeMaxDynamicSharedMemorySize, FSMEM);

    int nx4 = MROWS * DM / 4, nw4 = DM * DM / 4;
    f2h_k<<<(nx4 + 255) / 256, 256>>>(x, xh, nx4);
    f2h4_k<<<dim3((nw4 + 255) / 256, 4), 256>>>(Wq, Wk, Wv, Wo,
                                                wqh, wkh, wvh, woh, nw4);
    rope_fill<<<256, 256>>>(pos);

    gemm_qkv<<<dim3(DM / 128, MROWS / 128, 3), 256, GSMEM>>>(
        xh, wqh, wkh, wvh, qh, kh, vth);

    flash_h<<<dim3(SEQ / 128, BATCH * NH), 256, FSMEM>>>(qh, kh, vth, ath);

    gemm_out<<<dim3(DM / 128, MROWS / 128), 256, GSMEM>>>(ath, woh, out);
}

// round 11
// speedup vs baseline: 6.2389x; 1.0576x over previous
#include <cuda_runtime.h>
#include <cuda_fp16.h>
#include <math.h>
#include <stdint.h>

#define BATCH 2
#define SEQ   2048
#define NH    16
#define HD    64
#define DM    1024
#define MROWS (BATCH*SEQ)   /* 4096 */

/* ------------------------------------------------------------------ */
/* scratch                                                             */
/* ------------------------------------------------------------------ */
__device__ __half g_xh [(size_t)MROWS * DM];
__device__ __half g_wqh[(size_t)DM * DM];
__device__ __half g_wkh[(size_t)DM * DM];
__device__ __half g_wvh[(size_t)DM * DM];
__device__ __half g_woh[(size_t)DM * DM];
__device__ __half g_qh [(size_t)BATCH * NH * SEQ * HD]; /* [b,h,s,d], pre-scaled 1/8 */
__device__ __half g_kh [(size_t)BATCH * NH * SEQ * HD]; /* [b,h,s,d] */
__device__ __half g_vth[(size_t)BATCH * NH * HD * SEQ]; /* [b,h,d,s] */
__device__ __half g_ath[(size_t)MROWS * DM];            /* [b,s,h*d] */
__device__ float  g_rope[SEQ * 32 * 2];

/* ------------------------------------------------------------------ */
/* helpers                                                             */
/* ------------------------------------------------------------------ */
__device__ __forceinline__ uint32_t smem_u32(const void* p)
{
    uint32_t a;
    asm("{ .reg .u64 t; cvta.to.shared.u64 t, %1; cvt.u32.u64 %0, t; }"
        : "=r"(a) : "l"(p));
    return a;
}

__device__ __forceinline__ void cpa16(uint32_t dst, const void* src)
{
    asm volatile("cp.async.cg.shared.global [%0], [%1], 16;" :: "r"(dst), "l"(src));
}
#define CP_COMMIT() asm volatile("cp.async.commit_group;" ::: "memory")
#define CP_WAIT0()  asm volatile("cp.async.wait_group 0;" ::: "memory")
#define CP_WAIT1()  asm volatile("cp.async.wait_group 1;" ::: "memory")

__device__ __forceinline__ void mma16(float* c, uint32_t a0, uint32_t a1,
                                      uint32_t a2, uint32_t a3,
                                      uint32_t b0, uint32_t b1)
{
    asm("mma.sync.aligned.m16n8k16.row.col.f32.f16.f16.f32 "
        "{%0,%1,%2,%3},{%4,%5,%6,%7},{%8,%9},{%0,%1,%2,%3};"
        : "+f"(c[0]), "+f"(c[1]), "+f"(c[2]), "+f"(c[3])
        : "r"(a0), "r"(a1), "r"(a2), "r"(a3), "r"(b0), "r"(b1));
}

__device__ __forceinline__ void ldm4(uint32_t* r, uint32_t addr)
{
    asm volatile("ldmatrix.sync.aligned.m8n8.x4.shared.b16 {%0,%1,%2,%3}, [%4];"
        : "=r"(r[0]), "=r"(r[1]), "=r"(r[2]), "=r"(r[3]) : "r"(addr));
}

__device__ __forceinline__ uint32_t h2pack(float a, float b)
{
    __half2 h = __floats2half2_rn(a, b);
    return *(uint32_t*)&h;
}

/* ------------------------------------------------------------------ */
/* prepass                                                             */
/* ------------------------------------------------------------------ */
__global__ void f2h_k(const float* __restrict__ src, __half* __restrict__ dst, int n4)
{
    int i = blockIdx.x * blockDim.x + threadIdx.x;
    if (i >= n4) return;
    float4 v = ((const float4*)src)[i];
    ((uint2*)dst)[i] = make_uint2(h2pack(v.x, v.y), h2pack(v.z, v.w));
}

__global__ void f2h4_k(const float* s0, const float* s1, const float* s2,
                       const float* s3, __half* d0, __half* d1, __half* d2,
                       __half* d3, int n4)
{
    int i = blockIdx.x * blockDim.x + threadIdx.x;
    if (i >= n4) return;
    const float* s; __half* d;
    switch (blockIdx.y) {
        case 0: s = s0; d = d0; break;
        case 1: s = s1; d = d1; break;
        case 2: s = s2; d = d2; break;
        default: s = s3; d = d3; break;
    }
    float4 v = ((const float4*)s)[i];
    ((uint2*)d)[i] = make_uint2(h2pack(v.x, v.y), h2pack(v.z, v.w));
}

__global__ void rope_fill(const int* __restrict__ pos)
{
    int idx = blockIdx.x * blockDim.x + threadIdx.x;
    if (idx >= SEQ * 32) return;
    int s = idx >> 5, p = idx & 31;
    float ff  = (float)(1.0 / pow(10000.0, (double)(2 * p) / 64.0));
    float ang = (float)pos[s] * ff;
    double a  = (double)ang;
    g_rope[idx * 2 + 0] = (float)cos(a);
    g_rope[idx * 2 + 1] = (float)sin(a);
}

/* ------------------------------------------------------------------ */
/* fp16 GEMM: 128x128 tile, BK=64, 2-stage cp.async, ldmatrix frags.   */
/* mode 0: fp32 row-major; 1: Q rope*0.125 [b,h,s,d];                  */
/* mode 2: K rope [b,h,s,d]; 3: V fp16 [b,h,d,s]                       */
/* ------------------------------------------------------------------ */
#define GBK   64
#define KSH   72                     /* halfs: 144B ≡ 16 mod 128 -> cf */
#define ABUFH (128 * KSH)            /* 9216 halfs */
#define STGH  (2 * ABUFH)            /* per stage A+B */
#define NCH   (DM / GBK)             /* 16 */
#define GSMEM (2 * STGH * 2)         /* 73728 B */

__device__ __forceinline__ void gemm_body(const __half* __restrict__ A,
                                          const __half* __restrict__ Bw,
                                          void* __restrict__ Cp, int mode,
                                          __half* hsm, int m0, int n0)
{
    uint32_t sbase = smem_u32(hsm);
    int t = threadIdx.x, lane = t & 31, w = t >> 5;
    int g = lane >> 2, tq = lane & 3;
    int wm = (w & 1) * 64, wn = (w >> 1) * 32;

    float acc[4][4][4];
#pragma unroll
    for (int mf = 0; mf < 4; mf++)
#pragma unroll
        for (int nf = 0; nf < 4; nf++)
#pragma unroll
            for (int i = 0; i < 4; i++) acc[mf][nf][i] = 0.0f;

    int arow = (lane & 7) + ((lane >> 3) & 1) * 8;
    int akoff = (lane >> 4) * 8;
    int brow = (lane & 7) + ((lane >> 4) & 1) * 8;
    int bkoff = ((lane >> 3) & 1) * 8;
    uint32_t a_off[4], b_off[2];
#pragma unroll
    for (int mf = 0; mf < 4; mf++)
        a_off[mf] = ((wm + mf * 16 + arow) * KSH + akoff) * 2;
#pragma unroll
    for (int p = 0; p < 2; p++)
        b_off[p] = ((wn + p * 16 + brow) * KSH + bkoff) * 2 + ABUFH * 2;

    /* copy helper: chunk cn into stage st */
#define G_LOAD(cn, st) do {                                                   \
        uint32_t sa = sbase + (uint32_t)(st) * (STGH * 2);                    \
        uint32_t sbb = sa + ABUFH * 2;                                        \
        _Pragma("unroll")                                                     \
        for (int i = 0; i < 4; i++) {                                         \
            int idx = i * 256 + t, row = idx >> 3, c8 = idx & 7;              \
            cpa16(sa  + row * (KSH * 2) + c8 * 16,                            \
                  A  + (size_t)(m0 + row) * DM + (cn) * GBK + c8 * 8);        \
            cpa16(sbb + row * (KSH * 2) + c8 * 16,                            \
                  Bw + (size_t)(n0 + row) * DM + (cn) * GBK + c8 * 8);        \
        }                                                                     \
        CP_COMMIT();                                                          \
    } while (0)

    G_LOAD(0, 0);
    G_LOAD(1, 1);

#pragma unroll 1
    for (int c = 0; c < NCH; c++) {
        if (c < NCH - 1) CP_WAIT1(); else CP_WAIT0();
        __syncthreads();

        uint32_t stb = sbase + (uint32_t)(c & 1) * (STGH * 2);
#pragma unroll
        for (int ks = 0; ks < 4; ks++) {
            uint32_t kb = ks * 32;
            uint32_t af[4][4], bf[2][4];
#pragma unroll
            for (int mf = 0; mf < 4; mf++) ldm4(af[mf], stb + a_off[mf] + kb);
#pragma unroll
            for (int p = 0; p < 2; p++)    ldm4(bf[p], stb + b_off[p] + kb);
#pragma unroll
            for (int mf = 0; mf < 4; mf++)
#pragma unroll
                for (int nf = 0; nf < 4; nf++)
                    mma16(acc[mf][nf], af[mf][0], af[mf][1], af[mf][2], af[mf][3],
                          bf[nf >> 1][(nf & 1) * 2], bf[nf >> 1][(nf & 1) * 2 + 1]);
        }
        __syncthreads();
        if (c + 2 < NCH) G_LOAD(c + 2, c & 1);
    }
#undef G_LOAD

    if (mode == 3) {
        float* stg = (float*)hsm + w * (32 * 33);
        int bb = m0 >> 11;
        int gn = n0 + wn + lane;
        int hh = gn >> 6, dd = gn & 63;
#pragma unroll
        for (int hf = 0; hf < 2; hf++) {
#pragma unroll
            for (int mfl = 0; mfl < 2; mfl++) {
                int mf = hf * 2 + mfl;
                int rl = mfl * 16 + g;
#pragma unroll
                for (int nf = 0; nf < 4; nf++) {
                    int cl = nf * 8 + 2 * tq;
                    stg[rl * 33 + cl]           = acc[mf][nf][0];
                    stg[rl * 33 + cl + 1]       = acc[mf][nf][1];
                    stg[(rl + 8) * 33 + cl]     = acc[mf][nf][2];
                    stg[(rl + 8) * 33 + cl + 1] = acc[mf][nf][3];
                }
            }
            __syncwarp();
            int s0 = (m0 + wm + hf * 32) & (SEQ - 1);
            uint32_t u[16];
#pragma unroll
            for (int i = 0; i < 16; i++)
                u[i] = h2pack(stg[(2 * i) * 33 + lane], stg[(2 * i + 1) * 33 + lane]);
            uint4* dv = (uint4*)((__half*)Cp +
                        ((size_t)(bb * NH + hh) * HD + dd) * SEQ + s0);
            dv[0] = make_uint4(u[0],  u[1],  u[2],  u[3]);
            dv[1] = make_uint4(u[4],  u[5],  u[6],  u[7]);
            dv[2] = make_uint4(u[8],  u[9],  u[10], u[11]);
            dv[3] = make_uint4(u[12], u[13], u[14], u[15]);
            __syncwarp();
        }
        return;
    }

    float qscale = (mode == 1) ? 0.125f : 1.0f;
#pragma unroll
    for (int mf = 0; mf < 4; mf++)
#pragma unroll
        for (int i2 = 0; i2 < 2; i2++) {
            int gm = m0 + wm + mf * 16 + g + i2 * 8;
#pragma unroll
            for (int nf = 0; nf < 4; nf++) {
                int gn = n0 + wn + nf * 8 + 2 * tq;
                float v0 = acc[mf][nf][i2 * 2 + 0];
                float v1 = acc[mf][nf][i2 * 2 + 1];
                if (mode == 0) {
                    *(float2*)((float*)Cp + (size_t)gm * DM + gn) = make_float2(v0, v1);
                } else {
                    int bb = gm >> 11, ss = gm & (SEQ - 1);
                    int hh = gn >> 6,  dd = gn & 63;
                    int p = dd >> 1;
                    float cv = g_rope[(ss * 32 + p) * 2 + 0];
                    float sv = g_rope[(ss * 32 + p) * 2 + 1];
                    uint32_t h = h2pack((v0 * cv - v1 * sv) * qscale,
                                        (v0 * sv + v1 * cv) * qscale);
                    *(uint32_t*)((__half*)Cp +
                        (((size_t)(bb * NH + hh) * SEQ) + ss) * HD + dd) = h;
                }
            }
        }
}

__global__ __launch_bounds__(256, 2) void gemm_qkv(const __half* __restrict__ xh,
    const __half* __restrict__ wq, const __half* __restrict__ wk,
    const __half* __restrict__ wv, __half* __restrict__ qh,
    __half* __restrict__ kh, __half* __restrict__ vth)
{
    extern __shared__ __half hsm[];
    const __half* Bw; void* Cp; int mode;
    if (blockIdx.z == 0)      { Bw = wq; Cp = qh;  mode = 1; }
    else if (blockIdx.z == 1) { Bw = wk; Cp = kh;  mode = 2; }
    else                      { Bw = wv; Cp = vth; mode = 3; }
    gemm_body(xh, Bw, Cp, mode, hsm, blockIdx.y * 128, blockIdx.x * 128);
}

__global__ __launch_bounds__(256, 2) void gemm_out(const __half* __restrict__ A,
    const __half* __restrict__ Bw, float* __restrict__ C)
{
    extern __shared__ __half hsm[];
    gemm_body(A, Bw, C, 0, hsm, blockIdx.y * 128, blockIdx.x * 128);
}

/* ------------------------------------------------------------------ */
/* fp16 flash. 128 q/block, 8 warps. 128 keys per buffered iteration   */
/* (two 64-key sub-tiles). Q pre-scaled by 1/8 at projection.          */
/* ------------------------------------------------------------------ */
#define FQS 72                     /* Q/K stride (halfs) */
#define FVS 136                    /* V stride (halfs): 272B ≡ 16 mod 128 */
#define FOFF_K (128 * FQS)                 /* after Q */
#define FOFF_V (FOFF_K + 2 * 128 * FQS)    /* after K double buffer */
#define FSMEM  ((FOFF_V + 2 * 64 * FVS) * 2)   /* 90112 B */

__global__ __launch_bounds__(256) void flash_h(const __half* __restrict__ gq,
                                               const __half* __restrict__ gk,
                                               const __half* __restrict__ gv,
                                               __half* __restrict__ gout)
{
    extern __shared__ __half fsm[];
    uint32_t sbase = smem_u32(fsm);

    int t = threadIdx.x, lane = t & 31, w = t >> 5;
    int g = lane >> 2, tq = lane & 3;
    int qt = gridDim.x - 1 - blockIdx.x;
    int bh = blockIdx.y;
    int qr = w * 16 + g;

    const __half* Qg = gq + ((size_t)bh * SEQ + qt * 128) * HD;
    const __half* Kg = gk + (size_t)bh * SEQ * HD;
    const __half* Vg = gv + (size_t)bh * HD * SEQ;

    /* load tile ktp into buffer nb: K 128 rows x 64 halfs, V 64 x 128 */
#define F_LOADKV(ktp, nb) do {                                                \
        const __half* Kn = Kg + (size_t)(ktp) * 128 * HD;                     \
        _Pragma("unroll")                                                     \
        for (int i = 0; i < 4; i++) {                                         \
            int idx = i * 256 + t, row = idx >> 3, c8 = idx & 7;              \
            cpa16(sbase + (FOFF_K + ((nb) * 128 + row) * FQS) * 2 + c8 * 16,  \
                  Kn + row * HD + c8 * 8);                                    \
        }                                                                     \
        _Pragma("unroll")                                                     \
        for (int i = 0; i < 4; i++) {                                         \
            int idx = i * 256 + t, row = idx >> 4, c16 = idx & 15;            \
            cpa16(sbase + (FOFF_V + ((nb) * 64 + row) * FVS) * 2 + c16 * 16,  \
                  Vg + (size_t)row * SEQ + (ktp) * 128 + c16 * 8);            \
        }                                                                     \
        CP_COMMIT();                                                          \
    } while (0)

#pragma unroll
    for (int i = 0; i < 4; i++) {
        int idx = i * 256 + t, row = idx >> 3, c8 = idx & 7;
        cpa16(sbase + row * (FQS * 2) + c8 * 16, Qg + row * HD + c8 * 8);
    }
    F_LOADKV(0, 0);

    int arow = (lane & 7) + ((lane >> 3) & 1) * 8;
    int akoff = (lane >> 4) * 8;
    int brow = (lane & 7) + ((lane >> 4) & 1) * 8;
    int bkoff = ((lane >> 3) & 1) * 8;
    uint32_t q_off = ((w * 16 + arow) * FQS + akoff) * 2;
    uint32_t k_off[4], v_off[4];
#pragma unroll
    for (int p = 0; p < 4; p++) {
        k_off[p] = ((p * 16 + brow) * FQS + bkoff) * 2;
        v_off[p] = ((p * 16 + brow) * FVS + bkoff) * 2;
    }

    uint32_t qa[4][4];
    float o[8][4];
#pragma unroll
    for (int nf = 0; nf < 8; nf++)
#pragma unroll
        for (int i = 0; i < 4; i++) o[nf][i] = 0.0f;
    float m0r = -1e30f, m1r = -1e30f, l0 = 0.0f, l1 = 0.0f;
    const unsigned FULL = 0xffffffffu;

    int nktp = qt + 1;
#pragma unroll 1
    for (int ktp = 0; ktp < nktp; ktp++) {
        CP_WAIT0();
        __syncthreads();
        if (ktp + 1 < nktp) F_LOADKV(ktp + 1, (ktp + 1) & 1);

        if (ktp == 0) {
#pragma unroll
            for (int ks = 0; ks < 4; ks++) ldm4(qa[ks], sbase + q_off + ks * 32);
        }

        uint32_t kbb = sbase + (FOFF_K + (ktp & 1) * 128 * FQS) * 2;
        uint32_t vbb = sbase + (FOFF_V + (ktp & 1) * 64 * FVS) * 2;

#pragma unroll
        for (int hlf = 0; hlf < 2; hlf++) {
            int kt64 = ktp * 2 + hlf;
            if (kt64 * 64 > qt * 128 + w * 16 + 15) continue;

            uint32_t kbase = kbb + hlf * (64 * FQS * 2);
            uint32_t vkoff = hlf * 128;   /* key offset in halfs*2 = bytes */

            /* S = Q K^T (Q pre-scaled) */
            float s[8][4];
#pragma unroll
            for (int nf = 0; nf < 8; nf++)
                s[nf][0] = s[nf][1] = s[nf][2] = s[nf][3] = 0.0f;
#pragma unroll
            for (int ks = 0; ks < 4; ks++) {
                uint32_t kr[4][4];
#pragma unroll
                for (int p = 0; p < 4; p++) ldm4(kr[p], kbase + k_off[p] + ks * 32);
#pragma unroll
                for (int nf = 0; nf < 8; nf++)
                    mma16(s[nf], qa[ks][0], qa[ks][1], qa[ks][2], qa[ks][3],
                          kr[nf >> 1][(nf & 1) * 2], kr[nf >> 1][(nf & 1) * 2 + 1]);
            }

            int gi0 = qt * 128 + w * 16 + g;
            if (kt64 * 64 + 63 > gi0) {   /* diagonal: mask */
#pragma unroll
                for (int nf = 0; nf < 8; nf++)
#pragma unroll
                    for (int j = 0; j < 4; j++) {
                        int col = kt64 * 64 + nf * 8 + 2 * tq + (j & 1);
                        int row = gi0 + (j >> 1) * 8;
                        if (col > row) s[nf][j] = -1e30f;
                    }
            }

            /* online softmax */
            float mt0 = -1e30f, mt1 = -1e30f;
#pragma unroll
            for (int nf = 0; nf < 8; nf++) {
                mt0 = fmaxf(mt0, fmaxf(s[nf][0], s[nf][1]));
                mt1 = fmaxf(mt1, fmaxf(s[nf][2], s[nf][3]));
            }
            mt0 = fmaxf(mt0, __shfl_xor_sync(FULL, mt0, 1));
            mt0 = fmaxf(mt0, __shfl_xor_sync(FULL, mt0, 2));
            mt1 = fmaxf(mt1, __shfl_xor_sync(FULL, mt1, 1));
            mt1 = fmaxf(mt1, __shfl_xor_sync(FULL, mt1, 2));
            float mn0 = fmaxf(m0r, mt0), mn1 = fmaxf(m1r, mt1);
            float al0 = __expf(m0r - mn0), al1 = __expf(m1r - mn1);
            float ps0 = 0.0f, ps1 = 0.0f;
#pragma unroll
            for (int nf = 0; nf < 8; nf++) {
                s[nf][0] = __expf(s[nf][0] - mn0);
                s[nf][1] = __expf(s[nf][1] - mn0);
                s[nf][2] = __expf(s[nf][2] - mn1);
                s[nf][3] = __expf(s[nf][3] - mn1);
                ps0 += s[nf][0] + s[nf][1];
                ps1 += s[nf][2] + s[nf][3];
            }
            ps0 += __shfl_xor_sync(FULL, ps0, 1);
            ps0 += __shfl_xor_sync(FULL, ps0, 2);
            ps1 += __shfl_xor_sync(FULL, ps1, 1);
            ps1 += __shfl_xor_sync(FULL, ps1, 2);
            l0 = l0 * al0 + ps0;  l1 = l1 * al1 + ps1;
            m0r = mn0;  m1r = mn1;
#pragma unroll
            for (int nf = 0; nf < 8; nf++) {
                o[nf][0] *= al0; o[nf][1] *= al0;
                o[nf][2] *= al1; o[nf][3] *= al1;
            }

            /* O += P V (P from registers) */
#pragma unroll
            for (int ks = 0; ks < 4; ks++) {
                uint32_t pa0 = h2pack(s[2 * ks][0],     s[2 * ks][1]);
                uint32_t pa1 = h2pack(s[2 * ks][2],     s[2 * ks][3]);
                uint32_t pa2 = h2pack(s[2 * ks + 1][0], s[2 * ks + 1][1]);
                uint32_t pa3 = h2pack(s[2 * ks + 1][2], s[2 * ks + 1][3]);
                uint32_t vr[4][4];
#pragma unroll
                for (int p = 0; p < 4; p++)
                    ldm4(vr[p], vbb + v_off[p] + vkoff + ks * 32);
#pragma unroll
                for (int nf = 0; nf < 8; nf++)
                    mma16(o[nf], pa0, pa1, pa2, pa3,
                          vr[nf >> 1][(nf & 1) * 2], vr[nf >> 1][(nf & 1) * 2 + 1]);
            }
        }
    }
#undef F_LOADKV

    int b = bh >> 4, h = bh & 15;
    float inv0 = 1.0f / l0, inv1 = 1.0f / l1;
    int s0 = qt * 128 + qr;
#pragma unroll
    for (int nf = 0; nf < 8; nf++) {
        int d = nf * 8 + 2 * tq;
        *(uint32_t*)(gout + ((size_t)b * SEQ + s0) * DM + h * 64 + d) =
            h2pack(o[nf][0] * inv0, o[nf][1] * inv0);
        *(uint32_t*)(gout + ((size_t)b * SEQ + s0 + 8) * DM + h * 64 + d) =
            h2pack(o[nf][2] * inv1, o[nf][3] * inv1);
    }
}

/* ------------------------------------------------------------------ */
extern "C" void kernel_launch(void* const* d_in, const int* in_sizes, int n_in,
                              void* d_out, int out_size)
{
    const float* x  = (const float*)d_in[0];
    const float* Wq = (const float*)d_in[1];
    const float* Wk = (const float*)d_in[2];
    const float* Wv = (const float*)d_in[3];
    const float* Wo = (const float*)d_in[4];
    const int*  pos = (const int*)d_in[6];
    float* out = (float*)d_out;

    __half *xh, *wqh, *wkh, *wvh, *woh, *qh, *kh, *vth, *ath;
    cudaGetSymbolAddress((void**)&xh,  g_xh);
    cudaGetSymbolAddress((void**)&wqh, g_wqh);
    cudaGetSymbolAddress((void**)&wkh, g_wkh);
    cudaGetSymbolAddress((void**)&wvh, g_wvh);
    cudaGetSymbolAddress((void**)&woh, g_woh);
    cudaGetSymbolAddress((void**)&qh,  g_qh);
    cudaGetSymbolAddress((void**)&kh,  g_kh);
    cudaGetSymbolAddress((void**)&vth, g_vth);
    cudaGetSymbolAddress((void**)&ath, g_ath);

    cudaFuncSetAttribute(gemm_qkv, cudaFuncAttributeMaxDynamicSharedMemorySize, GSMEM);
    cudaFuncSetAttribute(gemm_out, cudaFuncAttributeMaxDynamicSharedMemorySize, GSMEM);
    cudaFuncSetAttribute(flash_h,  cudaFuncAttributeMaxDynamicSharedMemorySize, FSMEM);

    int nx4 = MROWS * DM / 4, nw4 = DM * DM / 4;
    f2h_k<<<(nx4 + 255) / 256, 256>>>(x, xh, nx4);
    f2h4_k<<<dim3((nw4 + 255) / 256, 4), 256>>>(Wq, Wk, Wv, Wo,
                                                wqh, wkh, wvh, woh, nw4);
    rope_fill<<<256, 256>>>(pos);

    gemm_qkv<<<dim3(DM / 128, MROWS / 128, 3), 256, GSMEM>>>(
        xh, wqh, wkh, wvh, qh, kh, vth);

    flash_h<<<dim3(SEQ / 128, BATCH * NH), 256, FSMEM>>>(qh, kh, vth, ath);

    gemm_out<<<dim3(DM / 128, MROWS / 128), 256, GSMEM>>>(ath, woh, out);
}

// round 12
// speedup vs baseline: 6.2678x; 1.0046x over previous
#include <cuda_runtime.h>
#include <cuda_fp16.h>
#include <math.h>
#include <stdint.h>

#define BATCH 2
#define SEQ   2048
#define NH    16
#define HD    64
#define DM    1024
#define MROWS (BATCH*SEQ)   /* 4096 */

/* ------------------------------------------------------------------ */
/* scratch                                                             */
/* ------------------------------------------------------------------ */
__device__ __half g_xh [(size_t)MROWS * DM];
__device__ __half g_wqh[(size_t)DM * DM];
__device__ __half g_wkh[(size_t)DM * DM];
__device__ __half g_wvh[(size_t)DM * DM];
__device__ __half g_woh[(size_t)DM * DM];
__device__ __half g_qh [(size_t)BATCH * NH * SEQ * HD]; /* [b,h,s,d], *0.125*log2e */
__device__ __half g_kh [(size_t)BATCH * NH * SEQ * HD]; /* [b,h,s,d] */
__device__ __half g_vth[(size_t)BATCH * NH * HD * SEQ]; /* [b,h,d,s] */
__device__ __half g_ath[(size_t)MROWS * DM];            /* [b,s,h*d] */
__device__ float  g_rope[SEQ * 32 * 2];

/* ------------------------------------------------------------------ */
/* helpers                                                             */
/* ------------------------------------------------------------------ */
__device__ __forceinline__ uint32_t smem_u32(const void* p)
{
    uint32_t a;
    asm("{ .reg .u64 t; cvta.to.shared.u64 t, %1; cvt.u32.u64 %0, t; }"
        : "=r"(a) : "l"(p));
    return a;
}

__device__ __forceinline__ void cpa16(uint32_t dst, const void* src)
{
    asm volatile("cp.async.cg.shared.global [%0], [%1], 16;" :: "r"(dst), "l"(src));
}
#define CP_COMMIT() asm volatile("cp.async.commit_group;" ::: "memory")
#define CP_WAIT0()  asm volatile("cp.async.wait_group 0;" ::: "memory")
#define CP_WAIT1()  asm volatile("cp.async.wait_group 1;" ::: "memory")

__device__ __forceinline__ void mma16(float* c, uint32_t a0, uint32_t a1,
                                      uint32_t a2, uint32_t a3,
                                      uint32_t b0, uint32_t b1)
{
    asm("mma.sync.aligned.m16n8k16.row.col.f32.f16.f16.f32 "
        "{%0,%1,%2,%3},{%4,%5,%6,%7},{%8,%9},{%0,%1,%2,%3};"
        : "+f"(c[0]), "+f"(c[1]), "+f"(c[2]), "+f"(c[3])
        : "r"(a0), "r"(a1), "r"(a2), "r"(a3), "r"(b0), "r"(b1));
}

__device__ __forceinline__ void ldm4(uint32_t* r, uint32_t addr)
{
    asm volatile("ldmatrix.sync.aligned.m8n8.x4.shared.b16 {%0,%1,%2,%3}, [%4];"
        : "=r"(r[0]), "=r"(r[1]), "=r"(r[2]), "=r"(r[3]) : "r"(addr));
}

__device__ __forceinline__ uint32_t h2pack(float a, float b)
{
    __half2 h = __floats2half2_rn(a, b);
    return *(uint32_t*)&h;
}

/* ------------------------------------------------------------------ */
/* prepass                                                             */
/* ------------------------------------------------------------------ */
__global__ void f2h_k(const float* __restrict__ src, __half* __restrict__ dst, int n4)
{
    int i = blockIdx.x * blockDim.x + threadIdx.x;
    if (i >= n4) return;
    float4 v = ((const float4*)src)[i];
    ((uint2*)dst)[i] = make_uint2(h2pack(v.x, v.y), h2pack(v.z, v.w));
}

__global__ void f2h4_k(const float* s0, const float* s1, const float* s2,
                       const float* s3, __half* d0, __half* d1, __half* d2,
                       __half* d3, int n4)
{
    int i = blockIdx.x * blockDim.x + threadIdx.x;
    if (i >= n4) return;
    const float* s; __half* d;
    switch (blockIdx.y) {
        case 0: s = s0; d = d0; break;
        case 1: s = s1; d = d1; break;
        case 2: s = s2; d = d2; break;
        default: s = s3; d = d3; break;
    }
    float4 v = ((const float4*)s)[i];
    ((uint2*)d)[i] = make_uint2(h2pack(v.x, v.y), h2pack(v.z, v.w));
}

__global__ void rope_fill(const int* __restrict__ pos)
{
    int idx = blockIdx.x * blockDim.x + threadIdx.x;
    if (idx >= SEQ * 32) return;
    int s = idx >> 5, p = idx & 31;
    float ff  = (float)(1.0 / pow(10000.0, (double)(2 * p) / 64.0));
    float ang = (float)pos[s] * ff;
    double a  = (double)ang;
    g_rope[idx * 2 + 0] = (float)cos(a);
    g_rope[idx * 2 + 1] = (float)sin(a);
}

/* ------------------------------------------------------------------ */
/* fp16 GEMM: 128x128 tile, BK=64, 3-stage cp.async, 1 barrier/chunk.  */
/* mode 0: fp32 row-major; 1: Q rope*0.125*log2e [b,h,s,d];            */
/* mode 2: K rope [b,h,s,d]; 3: V fp16 [b,h,d,s]                       */
/* ------------------------------------------------------------------ */
#define GBK   64
#define KSH   72
#define ABUFH (128 * KSH)
#define STGH  (2 * ABUFH)
#define NSTG  3
#define NCH   (DM / GBK)             /* 16 */
#define GSMEM (NSTG * STGH * 2)      /* 110592 B */

__device__ __forceinline__ void gemm_body(const __half* __restrict__ A,
                                          const __half* __restrict__ Bw,
                                          void* __restrict__ Cp, int mode,
                                          __half* hsm, int m0, int n0)
{
    uint32_t sbase = smem_u32(hsm);
    int t = threadIdx.x, lane = t & 31, w = t >> 5;
    int g = lane >> 2, tq = lane & 3;
    int wm = (w & 1) * 64, wn = (w >> 1) * 32;

    float acc[4][4][4];
#pragma unroll
    for (int mf = 0; mf < 4; mf++)
#pragma unroll
        for (int nf = 0; nf < 4; nf++)
#pragma unroll
            for (int i = 0; i < 4; i++) acc[mf][nf][i] = 0.0f;

    int arow = (lane & 7) + ((lane >> 3) & 1) * 8;
    int akoff = (lane >> 4) * 8;
    int brow = (lane & 7) + ((lane >> 4) & 1) * 8;
    int bkoff = ((lane >> 3) & 1) * 8;
    uint32_t a_off[4], b_off[2];
#pragma unroll
    for (int mf = 0; mf < 4; mf++)
        a_off[mf] = ((wm + mf * 16 + arow) * KSH + akoff) * 2;
#pragma unroll
    for (int p = 0; p < 2; p++)
        b_off[p] = ((wn + p * 16 + brow) * KSH + bkoff) * 2 + ABUFH * 2;

#define G_LOAD(cn, st) do {                                                   \
        uint32_t sa = sbase + (uint32_t)(st) * (STGH * 2);                    \
        uint32_t sbb = sa + ABUFH * 2;                                        \
        _Pragma("unroll")                                                     \
        for (int i = 0; i < 4; i++) {                                         \
            int idx = i * 256 + t, row = idx >> 3, c8 = idx & 7;              \
            cpa16(sa  + row * (KSH * 2) + c8 * 16,                            \
                  A  + (size_t)(m0 + row) * DM + (cn) * GBK + c8 * 8);        \
            cpa16(sbb + row * (KSH * 2) + c8 * 16,                            \
                  Bw + (size_t)(n0 + row) * DM + (cn) * GBK + c8 * 8);        \
        }                                                                     \
        CP_COMMIT();                                                          \
    } while (0)

    G_LOAD(0, 0);
    G_LOAD(1, 1);

#pragma unroll 1
    for (int c = 0; c < NCH; c++) {
        CP_WAIT1();                     /* chunk c resident (pending <= 1)   */
        __syncthreads();                /* visibility + all done w/ c-1      */
        if (c + 2 < NCH) G_LOAD(c + 2, (c + 2) % NSTG);  /* overwrites c-1   */

        uint32_t stb = sbase + (uint32_t)(c % NSTG) * (STGH * 2);
#pragma unroll
        for (int ks = 0; ks < 4; ks++) {
            uint32_t kb = ks * 32;
            uint32_t af[4][4], bf[2][4];
#pragma unroll
            for (int mf = 0; mf < 4; mf++) ldm4(af[mf], stb + a_off[mf] + kb);
#pragma unroll
            for (int p = 0; p < 2; p++)    ldm4(bf[p], stb + b_off[p] + kb);
#pragma unroll
            for (int mf = 0; mf < 4; mf++)
#pragma unroll
                for (int nf = 0; nf < 4; nf++)
                    mma16(acc[mf][nf], af[mf][0], af[mf][1], af[mf][2], af[mf][3],
                          bf[nf >> 1][(nf & 1) * 2], bf[nf >> 1][(nf & 1) * 2 + 1]);
        }
    }
#undef G_LOAD
    __syncthreads();

    if (mode == 3) {
        float* stg = (float*)hsm + w * (32 * 33);
        int bb = m0 >> 11;
        int gn = n0 + wn + lane;
        int hh = gn >> 6, dd = gn & 63;
#pragma unroll
        for (int hf = 0; hf < 2; hf++) {
#pragma unroll
            for (int mfl = 0; mfl < 2; mfl++) {
                int mf = hf * 2 + mfl;
                int rl = mfl * 16 + g;
#pragma unroll
                for (int nf = 0; nf < 4; nf++) {
                    int cl = nf * 8 + 2 * tq;
                    stg[rl * 33 + cl]           = acc[mf][nf][0];
                    stg[rl * 33 + cl + 1]       = acc[mf][nf][1];
                    stg[(rl + 8) * 33 + cl]     = acc[mf][nf][2];
                    stg[(rl + 8) * 33 + cl + 1] = acc[mf][nf][3];
                }
            }
            __syncwarp();
            int s0 = (m0 + wm + hf * 32) & (SEQ - 1);
            uint32_t u[16];
#pragma unroll
            for (int i = 0; i < 16; i++)
                u[i] = h2pack(stg[(2 * i) * 33 + lane], stg[(2 * i + 1) * 33 + lane]);
            uint4* dv = (uint4*)((__half*)Cp +
                        ((size_t)(bb * NH + hh) * HD + dd) * SEQ + s0);
            dv[0] = make_uint4(u[0],  u[1],  u[2],  u[3]);
            dv[1] = make_uint4(u[4],  u[5],  u[6],  u[7]);
            dv[2] = make_uint4(u[8],  u[9],  u[10], u[11]);
            dv[3] = make_uint4(u[12], u[13], u[14], u[15]);
            __syncwarp();
        }
        return;
    }

    float qscale = (mode == 1) ? 0.125f * 1.4426950408889634f : 1.0f;
#pragma unroll
    for (int mf = 0; mf < 4; mf++)
#pragma unroll
        for (int i2 = 0; i2 < 2; i2++) {
            int gm = m0 + wm + mf * 16 + g + i2 * 8;
#pragma unroll
            for (int nf = 0; nf < 4; nf++) {
                int gn = n0 + wn + nf * 8 + 2 * tq;
                float v0 = acc[mf][nf][i2 * 2 + 0];
                float v1 = acc[mf][nf][i2 * 2 + 1];
                if (mode == 0) {
                    *(float2*)((float*)Cp + (size_t)gm * DM + gn) = make_float2(v0, v1);
                } else {
                    int bb = gm >> 11, ss = gm & (SEQ - 1);
                    int hh = gn >> 6,  dd = gn & 63;
                    int p = dd >> 1;
                    float cv = g_rope[(ss * 32 + p) * 2 + 0];
                    float sv = g_rope[(ss * 32 + p) * 2 + 1];
                    uint32_t h = h2pack((v0 * cv - v1 * sv) * qscale,
                                        (v0 * sv + v1 * cv) * qscale);
                    *(uint32_t*)((__half*)Cp +
                        (((size_t)(bb * NH + hh) * SEQ) + ss) * HD + dd) = h;
                }
            }
        }
}

__global__ __launch_bounds__(256, 2) void gemm_qkv(const __half* __restrict__ xh,
    const __half* __restrict__ wq, const __half* __restrict__ wk,
    const __half* __restrict__ wv, __half* __restrict__ qh,
    __half* __restrict__ kh, __half* __restrict__ vth)
{
    extern __shared__ __half hsm[];
    const __half* Bw; void* Cp; int mode;
    if (blockIdx.z == 0)      { Bw = wq; Cp = qh;  mode = 1; }
    else if (blockIdx.z == 1) { Bw = wk; Cp = kh;  mode = 2; }
    else                      { Bw = wv; Cp = vth; mode = 3; }
    gemm_body(xh, Bw, Cp, mode, hsm, blockIdx.y * 128, blockIdx.x * 128);
}

__global__ __launch_bounds__(256, 2) void gemm_out(const __half* __restrict__ A,
    const __half* __restrict__ Bw, float* __restrict__ C)
{
    extern __shared__ __half hsm[];
    gemm_body(A, Bw, C, 0, hsm, blockIdx.y * 128, blockIdx.x * 128);
}

/* ------------------------------------------------------------------ */
/* fp16 flash, base-2 softmax (log2e folded into Q). 128 q/block,      */
/* 8 warps, 128 keys per buffered iteration.                           */
/* ------------------------------------------------------------------ */
#define FQS 72
#define FVS 136
#define FOFF_K (128 * FQS)
#define FOFF_V (FOFF_K + 2 * 128 * FQS)
#define FSMEM  ((FOFF_V + 2 * 64 * FVS) * 2)   /* 90112 B */

__global__ __launch_bounds__(256) void flash_h(const __half* __restrict__ gq,
                                               const __half* __restrict__ gk,
                                               const __half* __restrict__ gv,
                                               __half* __restrict__ gout)
{
    extern __shared__ __half fsm[];
    uint32_t sbase = smem_u32(fsm);

    int t = threadIdx.x, lane = t & 31, w = t >> 5;
    int g = lane >> 2, tq = lane & 3;
    int qt = gridDim.x - 1 - blockIdx.x;
    int bh = blockIdx.y;
    int qr = w * 16 + g;

    const __half* Qg = gq + ((size_t)bh * SEQ + qt * 128) * HD;
    const __half* Kg = gk + (size_t)bh * SEQ * HD;
    const __half* Vg = gv + (size_t)bh * HD * SEQ;

#define F_LOADKV(ktp, nb) do {                                                \
        const __half* Kn = Kg + (size_t)(ktp) * 128 * HD;                     \
        _Pragma("unroll")                                                     \
        for (int i = 0; i < 4; i++) {                                         \
            int idx = i * 256 + t, row = idx >> 3, c8 = idx & 7;              \
            cpa16(sbase + (FOFF_K + ((nb) * 128 + row) * FQS) * 2 + c8 * 16,  \
                  Kn + row * HD + c8 * 8);                                    \
        }                                                                     \
        _Pragma("unroll")                                                     \
        for (int i = 0; i < 4; i++) {                                         \
            int idx = i * 256 + t, row = idx >> 4, c16 = idx & 15;            \
            cpa16(sbase + (FOFF_V + ((nb) * 64 + row) * FVS) * 2 + c16 * 16,  \
                  Vg + (size_t)row * SEQ + (ktp) * 128 + c16 * 8);            \
        }                                                                     \
        CP_COMMIT();                                                          \
    } while (0)

#pragma unroll
    for (int i = 0; i < 4; i++) {
        int idx = i * 256 + t, row = idx >> 3, c8 = idx & 7;
        cpa16(sbase + row * (FQS * 2) + c8 * 16, Qg + row * HD + c8 * 8);
    }
    F_LOADKV(0, 0);

    int arow = (lane & 7) + ((lane >> 3) & 1) * 8;
    int akoff = (lane >> 4) * 8;
    int brow = (lane & 7) + ((lane >> 4) & 1) * 8;
    int bkoff = ((lane >> 3) & 1) * 8;
    uint32_t q_off = ((w * 16 + arow) * FQS + akoff) * 2;
    uint32_t k_off[4], v_off[4];
#pragma unroll
    for (int p = 0; p < 4; p++) {
        k_off[p] = ((p * 16 + brow) * FQS + bkoff) * 2;
        v_off[p] = ((p * 16 + brow) * FVS + bkoff) * 2;
    }

    uint32_t qa[4][4];
    float o[8][4];
#pragma unroll
    for (int nf = 0; nf < 8; nf++)
#pragma unroll
        for (int i = 0; i < 4; i++) o[nf][i] = 0.0f;
    float m0r = -1e30f, m1r = -1e30f, l0 = 0.0f, l1 = 0.0f;
    const unsigned FULL = 0xffffffffu;

    int nktp = qt + 1;
#pragma unroll 1
    for (int ktp = 0; ktp < nktp; ktp++) {
        CP_WAIT0();
        __syncthreads();
        if (ktp + 1 < nktp) F_LOADKV(ktp + 1, (ktp + 1) & 1);

        if (ktp == 0) {
#pragma unroll
            for (int ks = 0; ks < 4; ks++) ldm4(qa[ks], sbase + q_off + ks * 32);
        }

        uint32_t kbb = sbase + (FOFF_K + (ktp & 1) * 128 * FQS) * 2;
        uint32_t vbb = sbase + (FOFF_V + (ktp & 1) * 64 * FVS) * 2;

#pragma unroll
        for (int hlf = 0; hlf < 2; hlf++) {
            int kt64 = ktp * 2 + hlf;
            if (kt64 * 64 > qt * 128 + w * 16 + 15) continue;

            uint32_t kbase = kbb + hlf * (64 * FQS * 2);
            uint32_t vkoff = hlf * 128;

            /* S = Q K^T (Q pre-scaled by 0.125*log2e) */
            float s[8][4];
#pragma unroll
            for (int nf = 0; nf < 8; nf++)
                s[nf][0] = s[nf][1] = s[nf][2] = s[nf][3] = 0.0f;
#pragma unroll
            for (int ks = 0; ks < 4; ks++) {
                uint32_t kr[4][4];
#pragma unroll
                for (int p = 0; p < 4; p++) ldm4(kr[p], kbase + k_off[p] + ks * 32);
#pragma unroll
                for (int nf = 0; nf < 8; nf++)
                    mma16(s[nf], qa[ks][0], qa[ks][1], qa[ks][2], qa[ks][3],
                          kr[nf >> 1][(nf & 1) * 2], kr[nf >> 1][(nf & 1) * 2 + 1]);
            }

            int gi0 = qt * 128 + w * 16 + g;
            if (kt64 * 64 + 63 > gi0) {
#pragma unroll
                for (int nf = 0; nf < 8; nf++)
#pragma unroll
                    for (int j = 0; j < 4; j++) {
                        int col = kt64 * 64 + nf * 8 + 2 * tq + (j & 1);
                        int row = gi0 + (j >> 1) * 8;
                        if (col > row) s[nf][j] = -1e30f;
                    }
            }

            /* online softmax, base 2 */
            float mt0 = -1e30f, mt1 = -1e30f;
#pragma unroll
            for (int nf = 0; nf < 8; nf++) {
                mt0 = fmaxf(mt0, fmaxf(s[nf][0], s[nf][1]));
                mt1 = fmaxf(mt1, fmaxf(s[nf][2], s[nf][3]));
            }
            mt0 = fmaxf(mt0, __shfl_xor_sync(FULL, mt0, 1));
            mt0 = fmaxf(mt0, __shfl_xor_sync(FULL, mt0, 2));
            mt1 = fmaxf(mt1, __shfl_xor_sync(FULL, mt1, 1));
            mt1 = fmaxf(mt1, __shfl_xor_sync(FULL, mt1, 2));
            float mn0 = fmaxf(m0r, mt0), mn1 = fmaxf(m1r, mt1);
            float al0 = exp2f(m0r - mn0), al1 = exp2f(m1r - mn1);
            float ps0 = 0.0f, ps1 = 0.0f;
#pragma unroll
            for (int nf = 0; nf < 8; nf++) {
                s[nf][0] = exp2f(s[nf][0] - mn0);
                s[nf][1] = exp2f(s[nf][1] - mn0);
                s[nf][2] = exp2f(s[nf][2] - mn1);
                s[nf][3] = exp2f(s[nf][3] - mn1);
                ps0 += s[nf][0] + s[nf][1];
                ps1 += s[nf][2] + s[nf][3];
            }
            ps0 += __shfl_xor_sync(FULL, ps0, 1);
            ps0 += __shfl_xor_sync(FULL, ps0, 2);
            ps1 += __shfl_xor_sync(FULL, ps1, 1);
            ps1 += __shfl_xor_sync(FULL, ps1, 2);
            l0 = l0 * al0 + ps0;  l1 = l1 * al1 + ps1;
            m0r = mn0;  m1r = mn1;
#pragma unroll
            for (int nf = 0; nf < 8; nf++) {
                o[nf][0] *= al0; o[nf][1] *= al0;
                o[nf][2] *= al1; o[nf][3] *= al1;
            }

            /* O += P V (P from registers) */
#pragma unroll
            for (int ks = 0; ks < 4; ks++) {
                uint32_t pa0 = h2pack(s[2 * ks][0],     s[2 * ks][1]);
                uint32_t pa1 = h2pack(s[2 * ks][2],     s[2 * ks][3]);
                uint32_t pa2 = h2pack(s[2 * ks + 1][0], s[2 * ks + 1][1]);
                uint32_t pa3 = h2pack(s[2 * ks + 1][2], s[2 * ks + 1][3]);
                uint32_t vr[4][4];
#pragma unroll
                for (int p = 0; p < 4; p++)
                    ldm4(vr[p], vbb + v_off[p] + vkoff + ks * 32);
#pragma unroll
                for (int nf = 0; nf < 8; nf++)
                    mma16(o[nf], pa0, pa1, pa2, pa3,
                          vr[nf >> 1][(nf & 1) * 2], vr[nf >> 1][(nf & 1) * 2 + 1]);
            }
        }
    }
#undef F_LOADKV

    int b = bh >> 4, h = bh & 15;
    float inv0 = 1.0f / l0, inv1 = 1.0f / l1;
    int s0 = qt * 128 + qr;
#pragma unroll
    for (int nf = 0; nf < 8; nf++) {
        int d = nf * 8 + 2 * tq;
        *(uint32_t*)(gout + ((size_t)b * SEQ + s0) * DM + h * 64 + d) =
            h2pack(o[nf][0] * inv0, o[nf][1] * inv0);
        *(uint32_t*)(gout + ((size_t)b * SEQ + s0 + 8) * DM + h * 64 + d) =
            h2pack(o[nf][2] * inv1, o[nf][3] * inv1);
    }
}

/* ------------------------------------------------------------------ */
extern "C" void kernel_launch(void* const* d_in, const int* in_sizes, int n_in,
                              void* d_out, int out_size)
{
    const float* x  = (const float*)d_in[0];
    const float* Wq = (const float*)d_in[1];
    const float* Wk = (const float*)d_in[2];
    const float* Wv = (const float*)d_in[3];
    const float* Wo = (const float*)d_in[4];
    const int*  pos = (const int*)d_in[6];
    float* out = (float*)d_out;

    __half *xh, *wqh, *wkh, *wvh, *woh, *qh, *kh, *vth, *ath;
    cudaGetSymbolAddress((void**)&xh,  g_xh);
    cudaGetSymbolAddress((void**)&wqh, g_wqh);
    cudaGetSymbolAddress((void**)&wkh, g_wkh);
    cudaGetSymbolAddress((void**)&wvh, g_wvh);
    cudaGetSymbolAddress((void**)&woh, g_woh);
    cudaGetSymbolAddress((void**)&qh,  g_qh);
    cudaGetSymbolAddress((void**)&kh,  g_kh);
    cudaGetSymbolAddress((void**)&vth, g_vth);
    cudaGetSymbolAddress((void**)&ath, g_ath);

    cudaFuncSetAttribute(gemm_qkv, cudaFuncAttributeMaxDynamicSharedMemorySize, GSMEM);
    cudaFuncSetAttribute(gemm_out, cudaFuncAttributeMaxDynamicSharedMemorySize, GSMEM);
    cudaFuncSetAttribute(flash_h,  cudaFuncAttributeMaxDynamicSharedMemorySize, FSMEM);

    int nx4 = MROWS * DM / 4, nw4 = DM * DM / 4;
    f2h_k<<<(nx4 + 255) / 256, 256>>>(x, xh, nx4);
    f2h4_k<<<dim3((nw4 + 255) / 256, 4), 256>>>(Wq, Wk, Wv, Wo,
                                                wqh, wkh, wvh, woh, nw4);
    rope_fill<<<256, 256>>>(pos);

    gemm_qkv<<<dim3(DM / 128, MROWS / 128, 3), 256, GSMEM>>>(
        xh, wqh, wkh, wvh, qh, kh, vth);

    flash_h<<<dim3(SEQ / 128, BATCH * NH), 256, FSMEM>>>(qh, kh, vth, ath);

    gemm_out<<<dim3(DM / 128, MROWS / 128), 256, GSMEM>>>(ath, woh, out);
}